// round 13
// baseline (speedup 1.0000x reference)
#include <cuda_runtime.h>
#include <math.h>
#include <stdint.h>

// ---------------- problem constants ----------------
#define PB 32
#define PT 512
#define PD 512
#define PH 8
#define PK 64
#define PDH 64
#define ROWS (PB*PT)           // 16384

// ---------------- scratch (device globals; no allocation) ----------------
__device__ float  g_nx  [ROWS*PD];
__device__ float  g_nkv [ROWS*PD];
__device__ float  g_q   [ROWS*PD];
__device__ float  g_k   [ROWS*PD];
__device__ float  g_v   [ROWS*PD];
__device__ float  g_o   [ROWS*PD];
__device__ float  g_h1  [ROWS*PD];
__device__ float  g_nh1 [ROWS*PD];
__device__ float  g_gv  [ROWS*4096];
__device__ double g_qwin[PB*PD];
__device__ double g_qpart[PB*8*PD];
__device__ float  g_read[PB*PD];
__device__ float  g_rope[PT*32*2];     // cos/sin table [t][i][2]

// ---------------- tf32 split helpers ----------------
__device__ __forceinline__ void split_tf32u(float x, uint32_t &hi, uint32_t &lo) {
    asm("cvt.rna.tf32.f32 %0, %1;" : "=r"(hi) : "f"(x));
    lo = __float_as_uint(__fsub_rn(x, __uint_as_float(hi)));
}

__device__ __forceinline__ void mma_tf32(float4 &d,
    uint32_t a0, uint32_t a1, uint32_t a2, uint32_t a3,
    uint32_t b0, uint32_t b1)
{
    asm volatile(
        "mma.sync.aligned.m16n8k8.row.col.f32.tf32.tf32.f32 "
        "{%0,%1,%2,%3}, {%4,%5,%6,%7}, {%8,%9}, {%0,%1,%2,%3};"
        : "+f"(d.x), "+f"(d.y), "+f"(d.z), "+f"(d.w)
        : "r"(a0), "r"(a1), "r"(a2), "r"(a3), "r"(b0), "r"(b1));
}

__device__ __forceinline__ void cp_async16(uint32_t dst, const void* src) {
    asm volatile("cp.async.ca.shared.global [%0], [%1], 16;\n" :: "r"(dst), "l"(src));
}

// Kahan compensated add with IEEE intrinsics
__device__ __forceinline__ void kahan_add(float &s, float &c, float x) {
    float y = __fsub_rn(x, c);
    float t = __fadd_rn(s, y);
    c = __fsub_rn(__fsub_rn(t, s), y);
    s = t;
}

__device__ __forceinline__ float silu_mulf(float g, float vl) {
    return g / (1.0f + expf(-g)) * vl;
}

// ---------------- GEMM geometry: 128x64 CTA tile, 3 CTAs/SM ----------------
#define BK 16
#define A_LD 20
#define B_LD 72                          // 64 + 8 pad (conflict-free frag loads)
#define A_PLANE (128*A_LD)               // 2560
#define B_PLANE (BK*B_LD)                // 1152
#define STAGE_FLOATS (A_PLANE + B_PLANE) // 3712
#define NSTAGE 3
#define GSMEM_BYTES (NSTAGE*STAGE_FLOATS*4)   // 44544 B
#define GEMM_GRID 444                    // 3 CTAs x 148 SMs, persistent

// ---------------- 3xTF32 tensor-core GEMM: persistent, cp.async 3-stage ----------------
// Warp layout: 8 warps = 4(m) x 2(n); warp tile 32m x 32n; mma m16n8k8.
template<bool BIAS, bool RES, bool ROPE, bool SILU>
__global__ void __launch_bounds__(256, 3) mma_gemm_kernel(
    const float* __restrict__ A, const float* __restrict__ A2,
    const float* __restrict__ Bm,
    const float* __restrict__ bias, const float* __restrict__ res,
    const float* __restrict__ rtab,
    float* __restrict__ C, int M, int N, int Kd, int lda)
{
    extern __shared__ float sm[];
    const uint32_t smem_u32 = (uint32_t)__cvta_generic_to_shared(sm);

    const int tid  = threadIdx.x;
    const int lane = tid & 31, warp = tid >> 5;
    const int wm = warp >> 1, wn = warp & 1;

    // staging mappings
    const int a_r = tid >> 1;              // 0..127
    const int a_c = (tid & 1) * 8;         // 0 or 8
    const int b_r = tid >> 4;              // 0..15
    const int b_c = (tid & 15) * 4;        // 0..60 (one float4 per thread)

    const int nk = Kd / BK;
    const int nrow = M >> 7;
    const int ntiles = nrow * (N >> 6);

    for (int tile = blockIdx.x; tile < ntiles; tile += GEMM_GRID) {
        const int row0 = (tile % nrow) << 7;
        const int col0 = (tile / nrow) << 6;

        float4 acc[2][4];
#pragma unroll
        for (int i = 0; i < 2; i++)
#pragma unroll
            for (int j = 0; j < 4; j++) acc[i][j] = make_float4(0.f, 0.f, 0.f, 0.f);

        auto issue_tile = [&](int it, int slot) {
            int k0 = it * BK;
            if (SILU) {
                size_t gi = (size_t)(row0 + a_r) * lda + k0 + a_c;
                float4 ga = *(const float4*)&A[gi];
                float4 gb = *(const float4*)&A[gi + 4];
                float4 va = *(const float4*)&A2[gi];
                float4 vb = *(const float4*)&A2[gi + 4];
                float4 u0 = make_float4(silu_mulf(ga.x, va.x), silu_mulf(ga.y, va.y),
                                        silu_mulf(ga.z, va.z), silu_mulf(ga.w, va.w));
                float4 u1 = make_float4(silu_mulf(gb.x, vb.x), silu_mulf(gb.y, vb.y),
                                        silu_mulf(gb.z, vb.z), silu_mulf(gb.w, vb.w));
                float* ap = sm + slot*STAGE_FLOATS + a_r*A_LD + a_c;
                *(float4*)(ap)     = u0;
                *(float4*)(ap + 4) = u1;
            } else {
                uint32_t abase = smem_u32 + (slot*STAGE_FLOATS + a_r*A_LD + a_c) * 4;
                const float* ag = &A[(size_t)(row0 + a_r) * lda + k0 + a_c];
                cp_async16(abase,      ag);
                cp_async16(abase + 16, ag + 4);
            }
            uint32_t bbase = smem_u32 + (slot*STAGE_FLOATS + A_PLANE + b_r*B_LD + b_c) * 4;
            const float* bg = &Bm[(size_t)(k0 + b_r) * N + col0 + b_c];
            cp_async16(bbase, bg);
            asm volatile("cp.async.commit_group;\n");
        };

        issue_tile(0, 0);
        issue_tile(1, 1);

        for (int it = 0; it < nk; it++) {
            if (it + 1 < nk) { asm volatile("cp.async.wait_group 1;\n"); }
            else             { asm volatile("cp.async.wait_group 0;\n"); }
            __syncthreads();
            if (it + 2 < nk) issue_tile(it + 2, (it + 2) % NSTAGE);

            const float* as = sm + (it % NSTAGE) * STAGE_FLOATS;
            const float* bs = as + A_PLANE;
#pragma unroll
            for (int kk = 0; kk < 2; kk++) {
                const int kb = kk * 8;
                uint32_t ahi[2][4], alo[2][4], bhi[4][2], blo[4][2];
#pragma unroll
                for (int tm = 0; tm < 2; tm++) {
                    int r0 = (wm*32 + tm*16 + (lane >> 2)) * A_LD;
                    int c0 = kb + (lane & 3);
                    split_tf32u(as[r0          + c0    ], ahi[tm][0], alo[tm][0]);
                    split_tf32u(as[r0 + 8*A_LD + c0    ], ahi[tm][1], alo[tm][1]);
                    split_tf32u(as[r0          + c0 + 4], ahi[tm][2], alo[tm][2]);
                    split_tf32u(as[r0 + 8*A_LD + c0 + 4], ahi[tm][3], alo[tm][3]);
                }
#pragma unroll
                for (int tn = 0; tn < 4; tn++) {
                    int c = wn*32 + tn*8 + (lane >> 2);
                    int r0 = (kb + (lane & 3)) * B_LD;
                    split_tf32u(bs[r0          + c], bhi[tn][0], blo[tn][0]);
                    split_tf32u(bs[r0 + 4*B_LD + c], bhi[tn][1], blo[tn][1]);
                }
#pragma unroll
                for (int tm = 0; tm < 2; tm++)
#pragma unroll
                    for (int tn = 0; tn < 4; tn++)
                        mma_tf32(acc[tm][tn], ahi[tm][0], ahi[tm][1], ahi[tm][2], ahi[tm][3],
                                 bhi[tn][0], bhi[tn][1]);
#pragma unroll
                for (int tm = 0; tm < 2; tm++)
#pragma unroll
                    for (int tn = 0; tn < 4; tn++)
                        mma_tf32(acc[tm][tn], ahi[tm][0], ahi[tm][1], ahi[tm][2], ahi[tm][3],
                                 blo[tn][0], blo[tn][1]);
#pragma unroll
                for (int tm = 0; tm < 2; tm++)
#pragma unroll
                    for (int tn = 0; tn < 4; tn++)
                        mma_tf32(acc[tm][tn], alo[tm][0], alo[tm][1], alo[tm][2], alo[tm][3],
                                 bhi[tn][0], bhi[tn][1]);
            }
        }

        // epilogue
#pragma unroll
        for (int tm = 0; tm < 2; tm++) {
            int r0 = row0 + wm*32 + tm*16 + (lane >> 2);
#pragma unroll
            for (int tn = 0; tn < 4; tn++) {
                int c0 = col0 + wn*32 + tn*8 + 2*(lane & 3);   // always even
                float2 v0 = make_float2(acc[tm][tn].x, acc[tm][tn].y);
                float2 v1 = make_float2(acc[tm][tn].z, acc[tm][tn].w);
                if (BIAS) {
                    v0.x += bias[c0]; v0.y += bias[c0+1];
                    v1.x += bias[c0]; v1.y += bias[c0+1];
                }
                if (RES) {
                    float2 r0v = *(const float2*)&res[(size_t)r0 * N + c0];
                    float2 r1v = *(const float2*)&res[(size_t)(r0+8) * N + c0];
                    v0.x += r0v.x; v0.y += r0v.y;
                    v1.x += r1v.x; v1.y += r1v.y;
                }
                if (ROPE) {
                    int i = (c0 & 63) >> 1;
                    int t0 = r0 & (PT - 1);
                    int t1 = (r0 + 8) & (PT - 1);
                    float2 cs0 = *(const float2*)&rtab[2*(t0*32 + i)];
                    float2 cs1 = *(const float2*)&rtab[2*(t1*32 + i)];
                    float x0 = v0.x, x1 = v0.y;
                    v0.x = x0*cs0.x - x1*cs0.y;
                    v0.y = x0*cs0.y + x1*cs0.x;
                    x0 = v1.x; x1 = v1.y;
                    v1.x = x0*cs1.x - x1*cs1.y;
                    v1.y = x0*cs1.y + x1*cs1.x;
                }
                *(float2*)&C[(size_t)r0 * N + c0]     = v0;
                *(float2*)&C[(size_t)(r0+8) * N + c0] = v1;
            }
        }
        __syncthreads();
    }
}

// ---------------- RMSNorm ----------------
__global__ void rmsnorm_kernel(const float* __restrict__ x,
                               const float* __restrict__ s1, float* __restrict__ o1,
                               const float* __restrict__ s2, float* __restrict__ o2)
{
    int row = blockIdx.x, tid = threadIdx.x;
    const float* xr = x + (size_t)row * PD;
    float v0 = xr[tid], v1 = xr[tid + 256];
    __shared__ float sred[256];
    sred[tid] = v0*v0 + v1*v1;
    __syncthreads();
    for (int s = 128; s >= 1; s >>= 1) {
        if (tid < s) sred[tid] += sred[tid + s];
        __syncthreads();
    }
    float inv = rsqrtf(sred[0] * (1.0f/512.0f) + 1e-6f);
    size_t base = (size_t)row * PD;
    o1[base + tid]       = v0 * inv * s1[tid];
    o1[base + tid + 256] = v1 * inv * s1[tid + 256];
    if (o2) {
        o2[base + tid]       = v0 * inv * s2[tid];
        o2[base + tid + 256] = v1 * inv * s2[tid + 256];
    }
}

// ---------------- RoPE table ----------------
__global__ void rope_table_kernel(float* __restrict__ tab)
{
    int idx = blockIdx.x * 256 + threadIdx.x;
    int t = idx >> 5, i = idx & 31;
    double freq = exp(-((double)(2*i) / 64.0) * 9.210340371976184);
    double ang = (double)t * freq;
    tab[2*idx    ] = (float)cos(ang);
    tab[2*idx + 1] = (float)sin(ang);
}

// ---------------- causal attention: 1 thread = 1 query row, float4 smem reads ----
__global__ void __launch_bounds__(128) attn_kernel(
    const float* __restrict__ q, const float* __restrict__ k,
    const float* __restrict__ v, float* __restrict__ o)
{
    const int BS = 32;
    __shared__ float Ks[BS][64];
    __shared__ float Vs[BS][64];
    int t = blockIdx.x * 128 + threadIdx.x;
    int h = blockIdx.y, b = blockIdx.z;
    const float* qrow = q + ((size_t)(b*PT + t) * PD + h*PDH);
    float qreg[64];
#pragma unroll
    for (int i = 0; i < 64; i++) qreg[i] = qrow[i];
    float m = -1e30f, l = 0.0f;
    float acc[64];
#pragma unroll
    for (int i = 0; i < 64; i++) acc[i] = 0.0f;

    int send = blockIdx.x * 128 + 128;
    for (int s0 = 0; s0 < send; s0 += BS) {
        __syncthreads();
        for (int i = threadIdx.x; i < BS*16; i += 128) {
            int rr = i >> 4; int cc = (i & 15) << 2;
            size_t goff = (size_t)(b*PT + s0 + rr) * PD + h*PDH + cc;
            *(float4*)&Ks[rr][cc] = *(const float4*)&k[goff];
            *(float4*)&Vs[rr][cc] = *(const float4*)&v[goff];
        }
        __syncthreads();
        int nval = t - s0 + 1;
        if (nval > BS) nval = BS;
        if (nval > 0) {
            float sc[BS];
            float tm = -1e30f;
#pragma unroll
            for (int j = 0; j < BS; j++) {
                float s = 0.0f;
#pragma unroll
                for (int d4 = 0; d4 < 16; d4++) {
                    float4 kv = *(const float4*)&Ks[j][d4*4];
                    s = fmaf(qreg[4*d4+0], kv.x, s);
                    s = fmaf(qreg[4*d4+1], kv.y, s);
                    s = fmaf(qreg[4*d4+2], kv.z, s);
                    s = fmaf(qreg[4*d4+3], kv.w, s);
                }
                s *= 0.125f;
                sc[j] = (j < nval) ? s : -1e30f;
                tm = fmaxf(tm, sc[j]);
            }
            float nm = fmaxf(m, tm);
            float csc = expf(m - nm);
            l *= csc;
#pragma unroll
            for (int d = 0; d < 64; d++) acc[d] *= csc;
#pragma unroll
            for (int j = 0; j < BS; j++) {
                float p = expf(sc[j] - nm);
                l += p;
#pragma unroll
                for (int d4 = 0; d4 < 16; d4++) {
                    float4 vv = *(const float4*)&Vs[j][d4*4];
                    acc[4*d4+0] = fmaf(p, vv.x, acc[4*d4+0]);
                    acc[4*d4+1] = fmaf(p, vv.y, acc[4*d4+1]);
                    acc[4*d4+2] = fmaf(p, vv.z, acc[4*d4+2]);
                    acc[4*d4+3] = fmaf(p, vv.w, acc[4*d4+3]);
                }
            }
            m = nm;
        }
    }
    float inv = 1.0f / l;
    float* orow = o + ((size_t)(b*PT + t) * PD + h*PDH);
#pragma unroll
    for (int i = 0; i < 64; i++) orow[i] = acc[i] * inv;
}

// ---------------- mean over T: two-stage f64 ----------------
__global__ void qwin_part_kernel(const float* __restrict__ h2, double* __restrict__ part)
{
    int b = blockIdx.y, chunk = blockIdx.x, d = threadIdx.x;
    double s = 0.0;
    int t0 = chunk * 64;
    for (int t = t0; t < t0 + 64; t++)
        s += (double)h2[((size_t)(b*PT + t)) * PD + d];
    part[((size_t)b*8 + chunk) * PD + d] = s;
}
__global__ void qwin_reduce_kernel(const double* __restrict__ part, double* __restrict__ qwin)
{
    int b = blockIdx.x, d = threadIdx.x;
    double s = 0.0;
    for (int c = 0; c < 8; c++) s += part[((size_t)b*8 + c) * PD + d];
    qwin[b*PD + d] = s * (1.0 / (double)PT);
}

// ---------------- episodic memory: Kahan-f32 heavy math, f64 scalars ----------------
__global__ void __launch_bounds__(512) episodic_kernel(
    const float* __restrict__ epi_keys, const float* __restrict__ epi_vals,
    const float* __restrict__ epi_age,  const float* __restrict__ epi_str,
    const float* __restrict__ rms_read,
    const float* __restrict__ Wwk, const float* __restrict__ bwk,
    const float* __restrict__ Wwv, const float* __restrict__ bwv,
    const float* __restrict__ Wws, const float* __restrict__ bws,
    const float* __restrict__ Wg1, const float* __restrict__ bg1,
    const float* __restrict__ Wg2, const float* __restrict__ bg2,
    const double* __restrict__ qwin,
    float* __restrict__ read_out,
    float* __restrict__ keys_new, float* __restrict__ vals_new,
    float* __restrict__ age_new,  float* __restrict__ sn_out,
    float* __restrict__ gate_out)
{
    int b = blockIdx.x;
    int tid = threadIdx.x;
    int warp = tid >> 5, lane = tid & 31;
    __shared__ float  qwf[512], wkf[512], wvf[512];
    __shared__ double sred[512];
    __shared__ double lg[64], wr[64];
    __shared__ float  swf[64];
    __shared__ double s_qninv, s_ws, s_wkinv;
    __shared__ float  s_best;
    __shared__ int    s_kstar;

    double qwd = qwin[b*PD + tid];
    qwf[tid] = (float)qwd;
    __syncthreads();

    sred[tid] = qwd*qwd;
    __syncthreads();
    for (int s = 256; s >= 1; s >>= 1) { if (tid < s) sred[tid] += sred[tid+s]; __syncthreads(); }
    if (tid == 0) s_qninv = 1.0 / (sqrt(sred[0]) + 1e-6);
    __syncthreads();

    {
        float a1 = 0.f, c1 = 0.f, a2 = 0.f, c2 = 0.f;
        for (int i = 0; i < 512; i++) {
            float qv = qwf[i];
            kahan_add(a1, c1, __fmul_rn(qv, Wwk[i*512 + tid]));
            kahan_add(a2, c2, __fmul_rn(qv, Wwv[i*512 + tid]));
        }
        wkf[tid] = __fadd_rn(a1, bwk[tid]);
        wvf[tid] = __fadd_rn(a2, bwv[tid]);
    }

    sred[tid] = qwd * (double)Wws[tid];
    __syncthreads();
    for (int s = 256; s >= 1; s >>= 1) { if (tid < s) sred[tid] += sred[tid+s]; __syncthreads(); }
    if (tid == 0) s_ws = 1.0 / (1.0 + exp(-(sred[0] + (double)bws[0])));
    __syncthreads();

    sred[tid] = (double)wkf[tid] * (double)wkf[tid];
    __syncthreads();
    for (int s = 256; s >= 1; s >>= 1) { if (tid < s) sred[tid] += sred[tid+s]; __syncthreads(); }
    if (tid == 0) s_wkinv = 1.0 / (sqrt(sred[0]) + 1e-6);
    __syncthreads();

    for (int kk = warp; kk < PK; kk += 16) {
        const float* kp = epi_keys + (size_t)(b*PK + kk) * PD;
        float ss = 0.f, ssc = 0.f, dq = 0.f, dqc = 0.f, dw = 0.f, dwc = 0.f;
        for (int d = lane; d < 512; d += 32) {
            float kv = kp[d];
            kahan_add(ss, ssc, __fmul_rn(kv, kv));
            kahan_add(dq, dqc, __fmul_rn(kv, qwf[d]));
            kahan_add(dw, dwc, __fmul_rn(kv, wkf[d]));
        }
#pragma unroll
        for (int o = 16; o > 0; o >>= 1) {
            ss += __shfl_xor_sync(0xffffffffu, ss, o);
            dq += __shfl_xor_sync(0xffffffffu, dq, o);
            dw += __shfl_xor_sync(0xffffffffu, dw, o);
        }
        if (lane == 0) {
            double kninv = 1.0 / (sqrt((double)ss) + 1e-6);
            double simr  = (double)dq * kninv * s_qninv;
            double st    = (double)epi_str[b*PK + kk];
            double stc   = fmin(fmax(st, 0.001), 1e9);
            lg[kk] = simr + 0.5*log(stc) - 0.02*(double)epi_age[b*PK + kk]
                   + ((st > 0.001) ? 0.0 : -1000.0);
            swf[kk] = (float)((double)dw * kninv * s_wkinv);
        }
    }
    __syncthreads();

    if (tid == 0) {
        double mx = -1e300;
        for (int kk = 0; kk < PK; kk++) mx = fmax(mx, lg[kk]);
        double sm = 0.0;
        for (int kk = 0; kk < PK; kk++) { double e = exp(lg[kk]-mx); wr[kk] = e; sm += e; }
        double inv = 1.0 / sm;
        for (int kk = 0; kk < PK; kk++) wr[kk] *= inv;
        float bs = -1e30f; int kst = 0;
        for (int kk = 0; kk < PK; kk++) if (swf[kk] > bs) { bs = swf[kk]; kst = kk; }
        s_best = bs; s_kstar = kst;
    }
    __syncthreads();

    float r = 0.f, rc = 0.f;
    for (int kk = 0; kk < PK; kk++)
        kahan_add(r, rc, __fmul_rn((float)wr[kk], epi_vals[(size_t)(b*PK + kk)*PD + tid]));
    sred[tid] = (double)r * (double)r;
    __syncthreads();
    for (int s = 256; s >= 1; s >>= 1) { if (tid < s) sred[tid] += sred[tid+s]; __syncthreads(); }
    double rinv = 1.0 / sqrt(sred[0] * (1.0/512.0) + 1e-6);
    read_out[b*PD + tid] = (float)((double)r * rinv * (double)rms_read[tid]);
    __syncthreads();

    float ws = (float)s_ws; int kstar = s_kstar;

    for (int kk = warp; kk < PK; kk += 16) {
        float re = (kk == kstar) ? ws * 0.5f : 0.0f;
        const float* kp = epi_keys + (size_t)(b*PK + kk) * PD;
        const float* vp = epi_vals + (size_t)(b*PK + kk) * PD;
        float ss = 0.f;
        for (int d = lane; d < 512; d += 32) {
            float tk = (1.0f - re)*kp[d] + re*wkf[d];
            ss = fmaf(tk, tk, ss);
            vals_new[(size_t)(b*PK + kk)*PD + d] = (1.0f - re)*vp[d] + re*wvf[d];
        }
#pragma unroll
        for (int o = 16; o > 0; o >>= 1) ss += __shfl_xor_sync(0xffffffffu, ss, o);
        float ninv = (float)(1.0 / (sqrt((double)ss) + 1e-6));
        for (int d = lane; d < 512; d += 32) {
            float tk = (1.0f - re)*kp[d] + re*wkf[d];
            keys_new[(size_t)(b*PK + kk)*PD + d] = tk * ninv;
        }
    }

    if (tid < PK) {
        int kk = tid;
        float ww = (kk == kstar) ? 1.0f : 0.0f;
        age_new[b*PK + kk] = (epi_age[b*PK + kk] + 1.0f) * (1.0f - ww);
        float s0 = epi_str[b*PK + kk] * 0.995f;
        float snv = s0 + ww * ws * (1.0f - s0);
        sn_out[b*PK + kk] = fminf(fmaxf(snv, 0.001f), 1.0f);
    }

    {
        float nov = 1.0f - s_best;
        float hs = 0.f, hc = 0.f;
        for (int i = 0; i < 512; i++)
            kahan_add(hs, hc, __fmul_rn(qwf[i], Wg1[i*512 + tid]));
        kahan_add(hs, hc, __fmul_rn(ws,  Wg1[512*512 + tid]));
        kahan_add(hs, hc, __fmul_rn(nov, Wg1[513*512 + tid]));
        double hsum = (double)__fadd_rn(hs, bg1[tid]);
        double sil = hsum / (1.0 + exp(-hsum));
        sred[tid] = sil * (double)Wg2[tid];
    }
    __syncthreads();
    for (int s = 256; s >= 1; s >>= 1) { if (tid < s) sred[tid] += sred[tid+s]; __syncthreads(); }
    if (tid == 0) gate_out[b] = (float)(1.0 / (1.0 + exp(-(sred[0] + (double)bg2[0]))));
}

// ---------------- out += gate[b] * read[b, :] ----------------
__global__ void bcast_add_kernel(float* __restrict__ out,
                                 const float* __restrict__ read,
                                 const float* __restrict__ gate)
{
    size_t idx = (size_t)blockIdx.x * blockDim.x + threadIdx.x;
    int b = (int)(idx >> 18);
    int d = (int)(idx & 511);
    out[idx] += gate[b] * read[b*PD + d];
}

// ---------------- launch ----------------
extern "C" void kernel_launch(void* const* d_in, const int* in_sizes, int n_in,
                              void* d_out, int out_size)
{
    const float* x        = (const float*)d_in[0];
    const float* epi_keys = (const float*)d_in[1];
    const float* epi_vals = (const float*)d_in[2];
    const float* epi_age  = (const float*)d_in[3];
    const float* epi_str  = (const float*)d_in[4];
    const float* rms1     = (const float*)d_in[6];
    const float* rms_kv   = (const float*)d_in[7];
    const float* rms2     = (const float*)d_in[8];
    const float* rms_read = (const float*)d_in[9];
    const float* Wq = (const float*)d_in[10]; const float* bq = (const float*)d_in[11];
    const float* Wk = (const float*)d_in[12]; const float* bk = (const float*)d_in[13];
    const float* Wv = (const float*)d_in[14]; const float* bv = (const float*)d_in[15];
    const float* Wo = (const float*)d_in[16]; const float* bo = (const float*)d_in[17];
    const float* W1 = (const float*)d_in[18]; const float* W2 = (const float*)d_in[19];
    const float* Wwk = (const float*)d_in[20]; const float* bwk = (const float*)d_in[21];
    const float* Wwv = (const float*)d_in[22]; const float* bwv = (const float*)d_in[23];
    const float* Wws = (const float*)d_in[24]; const float* bws = (const float*)d_in[25];
    const float* Wg1 = (const float*)d_in[26]; const float* bg1 = (const float*)d_in[27];
    const float* Wg2 = (const float*)d_in[28]; const float* bg2 = (const float*)d_in[29];

    float *nx, *nkv, *q, *k, *v, *o, *h1, *nh1, *gv, *readb, *ropetab;
    double *qwin, *qpart;
    cudaGetSymbolAddress((void**)&nx,   g_nx);
    cudaGetSymbolAddress((void**)&nkv,  g_nkv);
    cudaGetSymbolAddress((void**)&q,    g_q);
    cudaGetSymbolAddress((void**)&k,    g_k);
    cudaGetSymbolAddress((void**)&v,    g_v);
    cudaGetSymbolAddress((void**)&o,    g_o);
    cudaGetSymbolAddress((void**)&h1,   g_h1);
    cudaGetSymbolAddress((void**)&nh1,  g_nh1);
    cudaGetSymbolAddress((void**)&gv,   g_gv);
    cudaGetSymbolAddress((void**)&qwin, g_qwin);
    cudaGetSymbolAddress((void**)&qpart,g_qpart);
    cudaGetSymbolAddress((void**)&readb,g_read);
    cudaGetSymbolAddress((void**)&ropetab, g_rope);

    float* out      = (float*)d_out;
    float* keys_new = out + (size_t)ROWS*PD;
    float* vals_new = keys_new + (size_t)PB*PK*PD;
    float* age_new  = vals_new + (size_t)PB*PK*PD;
    float* sn       = age_new + PB*PK;
    float* gate     = sn + PB*PK;

    cudaFuncSetAttribute(mma_gemm_kernel<true,false,true,false>,
                         cudaFuncAttributeMaxDynamicSharedMemorySize, GSMEM_BYTES);
    cudaFuncSetAttribute(mma_gemm_kernel<true,false,false,false>,
                         cudaFuncAttributeMaxDynamicSharedMemorySize, GSMEM_BYTES);
    cudaFuncSetAttribute(mma_gemm_kernel<true,true,false,false>,
                         cudaFuncAttributeMaxDynamicSharedMemorySize, GSMEM_BYTES);
    cudaFuncSetAttribute(mma_gemm_kernel<false,false,false,false>,
                         cudaFuncAttributeMaxDynamicSharedMemorySize, GSMEM_BYTES);
    cudaFuncSetAttribute(mma_gemm_kernel<false,true,false,true>,
                         cudaFuncAttributeMaxDynamicSharedMemorySize, GSMEM_BYTES);

    dim3 blk(256);
    dim3 pgrid(GEMM_GRID);

    rope_table_kernel<<<64, 256>>>(ropetab);
    rmsnorm_kernel<<<ROWS, 256>>>(x, rms1, nx, rms_kv, nkv);
    mma_gemm_kernel<true,false,true,false><<<pgrid, blk, GSMEM_BYTES>>>(
        nx,  nullptr, Wq, bq, nullptr, ropetab, q, ROWS, 512, 512, 512);
    mma_gemm_kernel<true,false,true,false><<<pgrid, blk, GSMEM_BYTES>>>(
        nkv, nullptr, Wk, bk, nullptr, ropetab, k, ROWS, 512, 512, 512);
    mma_gemm_kernel<true,false,false,false><<<pgrid, blk, GSMEM_BYTES>>>(
        nkv, nullptr, Wv, bv, nullptr, nullptr, v, ROWS, 512, 512, 512);
    attn_kernel<<<dim3(PT/128, PH, PB), 128>>>(q, k, v, o);
    mma_gemm_kernel<true,true,false,false><<<pgrid, blk, GSMEM_BYTES>>>(
        o, nullptr, Wo, bo, x, nullptr, h1, ROWS, 512, 512, 512);
    rmsnorm_kernel<<<ROWS, 256>>>(h1, rms2, nh1, nullptr, nullptr);
    mma_gemm_kernel<false,false,false,false><<<pgrid, blk, GSMEM_BYTES>>>(
        nh1, nullptr, W1, nullptr, nullptr, nullptr, gv, ROWS, 4096, 512, 512);
    mma_gemm_kernel<false,true,false,true><<<pgrid, blk, GSMEM_BYTES>>>(
        gv, gv + 2048, W2, nullptr, h1, nullptr, out, ROWS, 512, 2048, 4096);
    qwin_part_kernel<<<dim3(8, PB), 512>>>(out, qpart);
    qwin_reduce_kernel<<<PB, 512>>>(qpart, qwin);
    episodic_kernel<<<PB, 512>>>(epi_keys, epi_vals, epi_age, epi_str, rms_read,
                                 Wwk, bwk, Wwv, bwv, Wws, bws, Wg1, bg1, Wg2, bg2,
                                 qwin, readb, keys_new, vals_new, age_new, sn, gate);
    bcast_add_kernel<<<(ROWS*PD)/256, 256>>>(out, readb, gate);
}

// round 14
// speedup vs baseline: 1.0493x; 1.0493x over previous
#include <cuda_runtime.h>
#include <math.h>
#include <stdint.h>

// ---------------- problem constants ----------------
#define PB 32
#define PT 512
#define PD 512
#define PH 8
#define PK 64
#define PDH 64
#define ROWS (PB*PT)           // 16384

// ---------------- scratch (device globals; no allocation) ----------------
__device__ float  g_nx  [ROWS*PD];
__device__ float  g_nkv [ROWS*PD];
__device__ float  g_q   [ROWS*PD];
__device__ float  g_k   [ROWS*PD];
__device__ float  g_v   [ROWS*PD];
__device__ float  g_o   [ROWS*PD];
__device__ float  g_h1  [ROWS*PD];
__device__ float  g_nh1 [ROWS*PD];
__device__ float  g_gv  [ROWS*4096];
__device__ double g_qwin[PB*PD];
__device__ double g_qpart[PB*8*PD];
__device__ float  g_read[PB*PD];
__device__ float  g_rope[PT*32*2];     // cos/sin table [t][i][2]

// ---------------- tf32 split helpers ----------------
__device__ __forceinline__ void split_tf32u(float x, uint32_t &hi, uint32_t &lo) {
    asm("cvt.rna.tf32.f32 %0, %1;" : "=r"(hi) : "f"(x));
    lo = __float_as_uint(__fsub_rn(x, __uint_as_float(hi)));
}

__device__ __forceinline__ void mma_tf32(float4 &d,
    uint32_t a0, uint32_t a1, uint32_t a2, uint32_t a3,
    uint32_t b0, uint32_t b1)
{
    asm volatile(
        "mma.sync.aligned.m16n8k8.row.col.f32.tf32.tf32.f32 "
        "{%0,%1,%2,%3}, {%4,%5,%6,%7}, {%8,%9}, {%0,%1,%2,%3};"
        : "+f"(d.x), "+f"(d.y), "+f"(d.z), "+f"(d.w)
        : "r"(a0), "r"(a1), "r"(a2), "r"(a3), "r"(b0), "r"(b1));
}

__device__ __forceinline__ void cp_async16(uint32_t dst, const void* src) {
    asm volatile("cp.async.ca.shared.global [%0], [%1], 16;\n" :: "r"(dst), "l"(src));
}

// Kahan compensated add with IEEE intrinsics
__device__ __forceinline__ void kahan_add(float &s, float &c, float x) {
    float y = __fsub_rn(x, c);
    float t = __fadd_rn(s, y);
    c = __fsub_rn(__fsub_rn(t, s), y);
    s = t;
}

__device__ __forceinline__ float silu_mulf(float g, float vl) {
    return g / (1.0f + expf(-g)) * vl;
}

// ---------------- GEMM geometry (R12 proven optimum) ----------------
#define BK 16
#define A_LD 20
#define B_LD 136
#define A_PLANE (128*A_LD)
#define B_PLANE (BK*B_LD)
#define STAGE_FLOATS (A_PLANE + B_PLANE)
#define NSTAGE 3
#define GSMEM_BYTES (NSTAGE*STAGE_FLOATS*4)   // 56832 B
#define GEMM_GRID 296

// ---------------- 3xTF32 tensor-core GEMM: persistent, cp.async 3-stage ----------------
template<bool BIAS, bool RES, bool ROPE, bool SILU>
__global__ void __launch_bounds__(256, 2) mma_gemm_kernel(
    const float* __restrict__ A, const float* __restrict__ A2,
    const float* __restrict__ Bm,
    const float* __restrict__ bias, const float* __restrict__ res,
    const float* __restrict__ rtab,
    float* __restrict__ C, int M, int N, int Kd, int lda)
{
    extern __shared__ float sm[];
    const uint32_t smem_u32 = (uint32_t)__cvta_generic_to_shared(sm);

    const int tid  = threadIdx.x;
    const int lane = tid & 31, warp = tid >> 5;
    const int wm = warp >> 1, wn = warp & 1;

    const int a_r = tid >> 1;
    const int a_c = (tid & 1) * 8;
    const int b_r = tid >> 4;
    const int b_c = (tid & 15) * 8;

    const int nk = Kd / BK;
    const int nrow = M >> 7;
    const int ntiles = nrow * (N >> 7);

    for (int tile = blockIdx.x; tile < ntiles; tile += GEMM_GRID) {
        const int row0 = (tile % nrow) << 7;
        const int col0 = (tile / nrow) << 7;

        float4 acc[2][8];
#pragma unroll
        for (int i = 0; i < 2; i++)
#pragma unroll
            for (int j = 0; j < 8; j++) acc[i][j] = make_float4(0.f, 0.f, 0.f, 0.f);

        auto issue_tile = [&](int it, int slot) {
            int k0 = it * BK;
            if (SILU) {
                size_t gi = (size_t)(row0 + a_r) * lda + k0 + a_c;
                float4 ga = *(const float4*)&A[gi];
                float4 gb = *(const float4*)&A[gi + 4];
                float4 va = *(const float4*)&A2[gi];
                float4 vb = *(const float4*)&A2[gi + 4];
                float4 u0 = make_float4(silu_mulf(ga.x, va.x), silu_mulf(ga.y, va.y),
                                        silu_mulf(ga.z, va.z), silu_mulf(ga.w, va.w));
                float4 u1 = make_float4(silu_mulf(gb.x, vb.x), silu_mulf(gb.y, vb.y),
                                        silu_mulf(gb.z, vb.z), silu_mulf(gb.w, vb.w));
                float* ap = sm + slot*STAGE_FLOATS + a_r*A_LD + a_c;
                *(float4*)(ap)     = u0;
                *(float4*)(ap + 4) = u1;
            } else {
                uint32_t abase = smem_u32 + (slot*STAGE_FLOATS + a_r*A_LD + a_c) * 4;
                const float* ag = &A[(size_t)(row0 + a_r) * lda + k0 + a_c];
                cp_async16(abase,      ag);
                cp_async16(abase + 16, ag + 4);
            }
            uint32_t bbase = smem_u32 + (slot*STAGE_FLOATS + A_PLANE + b_r*B_LD + b_c) * 4;
            const float* bg = &Bm[(size_t)(k0 + b_r) * N + col0 + b_c];
            cp_async16(bbase,      bg);
            cp_async16(bbase + 16, bg + 4);
            asm volatile("cp.async.commit_group;\n");
        };

        issue_tile(0, 0);
        issue_tile(1, 1);

        for (int it = 0; it < nk; it++) {
            if (it + 1 < nk) { asm volatile("cp.async.wait_group 1;\n"); }
            else             { asm volatile("cp.async.wait_group 0;\n"); }
            __syncthreads();
            if (it + 2 < nk) issue_tile(it + 2, (it + 2) % NSTAGE);

            const float* as = sm + (it % NSTAGE) * STAGE_FLOATS;
            const float* bs = as + A_PLANE;
#pragma unroll
            for (int kk = 0; kk < 2; kk++) {
                const int kb = kk * 8;
                uint32_t ahi[2][4], alo[2][4], bhi[8][2], blo[8][2];
#pragma unroll
                for (int tm = 0; tm < 2; tm++) {
                    int r0 = (wm*32 + tm*16 + (lane >> 2)) * A_LD;
                    int c0 = kb + (lane & 3);
                    split_tf32u(as[r0          + c0    ], ahi[tm][0], alo[tm][0]);
                    split_tf32u(as[r0 + 8*A_LD + c0    ], ahi[tm][1], alo[tm][1]);
                    split_tf32u(as[r0          + c0 + 4], ahi[tm][2], alo[tm][2]);
                    split_tf32u(as[r0 + 8*A_LD + c0 + 4], ahi[tm][3], alo[tm][3]);
                }
#pragma unroll
                for (int tn = 0; tn < 8; tn++) {
                    int c = wn*64 + tn*8 + (lane >> 2);
                    int r0 = (kb + (lane & 3)) * B_LD;
                    split_tf32u(bs[r0          + c], bhi[tn][0], blo[tn][0]);
                    split_tf32u(bs[r0 + 4*B_LD + c], bhi[tn][1], blo[tn][1]);
                }
#pragma unroll
                for (int tm = 0; tm < 2; tm++)
#pragma unroll
                    for (int tn = 0; tn < 8; tn++)
                        mma_tf32(acc[tm][tn], ahi[tm][0], ahi[tm][1], ahi[tm][2], ahi[tm][3],
                                 bhi[tn][0], bhi[tn][1]);
#pragma unroll
                for (int tm = 0; tm < 2; tm++)
#pragma unroll
                    for (int tn = 0; tn < 8; tn++)
                        mma_tf32(acc[tm][tn], ahi[tm][0], ahi[tm][1], ahi[tm][2], ahi[tm][3],
                                 blo[tn][0], blo[tn][1]);
#pragma unroll
                for (int tm = 0; tm < 2; tm++)
#pragma unroll
                    for (int tn = 0; tn < 8; tn++)
                        mma_tf32(acc[tm][tn], alo[tm][0], alo[tm][1], alo[tm][2], alo[tm][3],
                                 bhi[tn][0], bhi[tn][1]);
            }
        }

        // epilogue
#pragma unroll
        for (int tm = 0; tm < 2; tm++) {
            int r0 = row0 + wm*32 + tm*16 + (lane >> 2);
#pragma unroll
            for (int tn = 0; tn < 8; tn++) {
                int c0 = col0 + wn*64 + tn*8 + 2*(lane & 3);
                float2 v0 = make_float2(acc[tm][tn].x, acc[tm][tn].y);
                float2 v1 = make_float2(acc[tm][tn].z, acc[tm][tn].w);
                if (BIAS) {
                    v0.x += bias[c0]; v0.y += bias[c0+1];
                    v1.x += bias[c0]; v1.y += bias[c0+1];
                }
                if (RES) {
                    float2 r0v = *(const float2*)&res[(size_t)r0 * N + c0];
                    float2 r1v = *(const float2*)&res[(size_t)(r0+8) * N + c0];
                    v0.x += r0v.x; v0.y += r0v.y;
                    v1.x += r1v.x; v1.y += r1v.y;
                }
                if (ROPE) {
                    int i = (c0 & 63) >> 1;
                    int t0 = r0 & (PT - 1);
                    int t1 = (r0 + 8) & (PT - 1);
                    float2 cs0 = *(const float2*)&rtab[2*(t0*32 + i)];
                    float2 cs1 = *(const float2*)&rtab[2*(t1*32 + i)];
                    float x0 = v0.x, x1 = v0.y;
                    v0.x = x0*cs0.x - x1*cs0.y;
                    v0.y = x0*cs0.y + x1*cs0.x;
                    x0 = v1.x; x1 = v1.y;
                    v1.x = x0*cs1.x - x1*cs1.y;
                    v1.y = x0*cs1.y + x1*cs1.x;
                }
                *(float2*)&C[(size_t)r0 * N + c0]     = v0;
                *(float2*)&C[(size_t)(r0+8) * N + c0] = v1;
            }
        }
        __syncthreads();
    }
}

// ---------------- RMSNorm ----------------
__global__ void rmsnorm_kernel(const float* __restrict__ x,
                               const float* __restrict__ s1, float* __restrict__ o1,
                               const float* __restrict__ s2, float* __restrict__ o2)
{
    int row = blockIdx.x, tid = threadIdx.x;
    const float* xr = x + (size_t)row * PD;
    float v0 = xr[tid], v1 = xr[tid + 256];
    __shared__ float sred[256];
    sred[tid] = v0*v0 + v1*v1;
    __syncthreads();
    for (int s = 128; s >= 1; s >>= 1) {
        if (tid < s) sred[tid] += sred[tid + s];
        __syncthreads();
    }
    float inv = rsqrtf(sred[0] * (1.0f/512.0f) + 1e-6f);
    size_t base = (size_t)row * PD;
    o1[base + tid]       = v0 * inv * s1[tid];
    o1[base + tid + 256] = v1 * inv * s1[tid + 256];
    if (o2) {
        o2[base + tid]       = v0 * inv * s2[tid];
        o2[base + tid + 256] = v1 * inv * s2[tid + 256];
    }
}

// ---------------- RoPE table ----------------
__global__ void rope_table_kernel(float* __restrict__ tab)
{
    int idx = blockIdx.x * 256 + threadIdx.x;
    int t = idx >> 5, i = idx & 31;
    double freq = exp(-((double)(2*i) / 64.0) * 9.210340371976184);
    double ang = (double)t * freq;
    tab[2*idx    ] = (float)cos(ang);
    tab[2*idx + 1] = (float)sin(ang);
}

// ---------------- causal attention: 1 thread/row, 64-key smem tiles, 32-key sub-batches ----
__global__ void __launch_bounds__(128) attn_kernel(
    const float* __restrict__ q, const float* __restrict__ k,
    const float* __restrict__ v, float* __restrict__ o)
{
    const int TS = 64;   // keys per smem tile (one sync pair each)
    __shared__ float Ks[TS][64];
    __shared__ float Vs[TS][64];
    int t = blockIdx.x * 128 + threadIdx.x;
    int h = blockIdx.y, b = blockIdx.z;
    const float* qrow = q + ((size_t)(b*PT + t) * PD + h*PDH);
    float qreg[64];
#pragma unroll
    for (int i = 0; i < 64; i++) qreg[i] = qrow[i];
    float m = -1e30f, l = 0.0f;
    float acc[64];
#pragma unroll
    for (int i = 0; i < 64; i++) acc[i] = 0.0f;

    int send = blockIdx.x * 128 + 128;   // exclusive key bound for this block
    for (int s0 = 0; s0 < send; s0 += TS) {
        __syncthreads();
        // load 64x64 K and V tiles: 1024 float4 each; 128 threads -> 8 iters per array
        for (int i = threadIdx.x; i < TS*16; i += 128) {
            int rr = i >> 4; int cc = (i & 15) << 2;
            size_t goff = (size_t)(b*PT + s0 + rr) * PD + h*PDH + cc;
            *(float4*)&Ks[rr][cc] = *(const float4*)&k[goff];
            *(float4*)&Vs[rr][cc] = *(const float4*)&v[goff];
        }
        __syncthreads();
        // two 32-key sub-batches, identical order/math to the BS=32 version
#pragma unroll
        for (int sub = 0; sub < TS; sub += 32) {
            int base = s0 + sub;
            if (base >= send) break;
            int nval = t - base + 1;
            if (nval > 32) nval = 32;
            if (nval <= 0) continue;
            float sc[32];
            float tm = -1e30f;
#pragma unroll
            for (int j = 0; j < 32; j++) {
                float s = 0.0f;
#pragma unroll
                for (int d4 = 0; d4 < 16; d4++) {
                    float4 kv = *(const float4*)&Ks[sub + j][d4*4];
                    s = fmaf(qreg[4*d4+0], kv.x, s);
                    s = fmaf(qreg[4*d4+1], kv.y, s);
                    s = fmaf(qreg[4*d4+2], kv.z, s);
                    s = fmaf(qreg[4*d4+3], kv.w, s);
                }
                s *= 0.125f;
                sc[j] = (j < nval) ? s : -1e30f;
                tm = fmaxf(tm, sc[j]);
            }
            float nm = fmaxf(m, tm);
            float csc = expf(m - nm);
            l *= csc;
#pragma unroll
            for (int d = 0; d < 64; d++) acc[d] *= csc;
#pragma unroll
            for (int j = 0; j < 32; j++) {
                float p = expf(sc[j] - nm);
                l += p;
#pragma unroll
                for (int d4 = 0; d4 < 16; d4++) {
                    float4 vv = *(const float4*)&Vs[sub + j][d4*4];
                    acc[4*d4+0] = fmaf(p, vv.x, acc[4*d4+0]);
                    acc[4*d4+1] = fmaf(p, vv.y, acc[4*d4+1]);
                    acc[4*d4+2] = fmaf(p, vv.z, acc[4*d4+2]);
                    acc[4*d4+3] = fmaf(p, vv.w, acc[4*d4+3]);
                }
            }
            m = nm;
        }
    }
    float inv = 1.0f / l;
    float* orow = o + ((size_t)(b*PT + t) * PD + h*PDH);
#pragma unroll
    for (int i = 0; i < 64; i++) orow[i] = acc[i] * inv;
}

// ---------------- mean over T: two-stage f64 ----------------
__global__ void qwin_part_kernel(const float* __restrict__ h2, double* __restrict__ part)
{
    int b = blockIdx.y, chunk = blockIdx.x, d = threadIdx.x;
    double s = 0.0;
    int t0 = chunk * 64;
    for (int t = t0; t < t0 + 64; t++)
        s += (double)h2[((size_t)(b*PT + t)) * PD + d];
    part[((size_t)b*8 + chunk) * PD + d] = s;
}
__global__ void qwin_reduce_kernel(const double* __restrict__ part, double* __restrict__ qwin)
{
    int b = blockIdx.x, d = threadIdx.x;
    double s = 0.0;
    for (int c = 0; c < 8; c++) s += part[((size_t)b*8 + c) * PD + d];
    qwin[b*PD + d] = s * (1.0 / (double)PT);
}

// ---------------- episodic memory: Kahan-f32 heavy math, f64 scalars ----------------
__global__ void __launch_bounds__(512) episodic_kernel(
    const float* __restrict__ epi_keys, const float* __restrict__ epi_vals,
    const float* __restrict__ epi_age,  const float* __restrict__ epi_str,
    const float* __restrict__ rms_read,
    const float* __restrict__ Wwk, const float* __restrict__ bwk,
    const float* __restrict__ Wwv, const float* __restrict__ bwv,
    const float* __restrict__ Wws, const float* __restrict__ bws,
    const float* __restrict__ Wg1, const float* __restrict__ bg1,
    const float* __restrict__ Wg2, const float* __restrict__ bg2,
    const double* __restrict__ qwin,
    float* __restrict__ read_out,
    float* __restrict__ keys_new, float* __restrict__ vals_new,
    float* __restrict__ age_new,  float* __restrict__ sn_out,
    float* __restrict__ gate_out)
{
    int b = blockIdx.x;
    int tid = threadIdx.x;
    int warp = tid >> 5, lane = tid & 31;
    __shared__ float  qwf[512], wkf[512], wvf[512];
    __shared__ double sred[512];
    __shared__ double lg[64], wr[64];
    __shared__ float  swf[64];
    __shared__ double s_qninv, s_ws, s_wkinv;
    __shared__ float  s_best;
    __shared__ int    s_kstar;

    double qwd = qwin[b*PD + tid];
    qwf[tid] = (float)qwd;
    __syncthreads();

    sred[tid] = qwd*qwd;
    __syncthreads();
    for (int s = 256; s >= 1; s >>= 1) { if (tid < s) sred[tid] += sred[tid+s]; __syncthreads(); }
    if (tid == 0) s_qninv = 1.0 / (sqrt(sred[0]) + 1e-6);
    __syncthreads();

    {
        float a1 = 0.f, c1 = 0.f, a2 = 0.f, c2 = 0.f;
        for (int i = 0; i < 512; i++) {
            float qv = qwf[i];
            kahan_add(a1, c1, __fmul_rn(qv, Wwk[i*512 + tid]));
            kahan_add(a2, c2, __fmul_rn(qv, Wwv[i*512 + tid]));
        }
        wkf[tid] = __fadd_rn(a1, bwk[tid]);
        wvf[tid] = __fadd_rn(a2, bwv[tid]);
    }

    sred[tid] = qwd * (double)Wws[tid];
    __syncthreads();
    for (int s = 256; s >= 1; s >>= 1) { if (tid < s) sred[tid] += sred[tid+s]; __syncthreads(); }
    if (tid == 0) s_ws = 1.0 / (1.0 + exp(-(sred[0] + (double)bws[0])));
    __syncthreads();

    sred[tid] = (double)wkf[tid] * (double)wkf[tid];
    __syncthreads();
    for (int s = 256; s >= 1; s >>= 1) { if (tid < s) sred[tid] += sred[tid+s]; __syncthreads(); }
    if (tid == 0) s_wkinv = 1.0 / (sqrt(sred[0]) + 1e-6);
    __syncthreads();

    for (int kk = warp; kk < PK; kk += 16) {
        const float* kp = epi_keys + (size_t)(b*PK + kk) * PD;
        float ss = 0.f, ssc = 0.f, dq = 0.f, dqc = 0.f, dw = 0.f, dwc = 0.f;
        for (int d = lane; d < 512; d += 32) {
            float kv = kp[d];
            kahan_add(ss, ssc, __fmul_rn(kv, kv));
            kahan_add(dq, dqc, __fmul_rn(kv, qwf[d]));
            kahan_add(dw, dwc, __fmul_rn(kv, wkf[d]));
        }
#pragma unroll
        for (int o = 16; o > 0; o >>= 1) {
            ss += __shfl_xor_sync(0xffffffffu, ss, o);
            dq += __shfl_xor_sync(0xffffffffu, dq, o);
            dw += __shfl_xor_sync(0xffffffffu, dw, o);
        }
        if (lane == 0) {
            double kninv = 1.0 / (sqrt((double)ss) + 1e-6);
            double simr  = (double)dq * kninv * s_qninv;
            double st    = (double)epi_str[b*PK + kk];
            double stc   = fmin(fmax(st, 0.001), 1e9);
            lg[kk] = simr + 0.5*log(stc) - 0.02*(double)epi_age[b*PK + kk]
                   + ((st > 0.001) ? 0.0 : -1000.0);
            swf[kk] = (float)((double)dw * kninv * s_wkinv);
        }
    }
    __syncthreads();

    if (tid == 0) {
        double mx = -1e300;
        for (int kk = 0; kk < PK; kk++) mx = fmax(mx, lg[kk]);
        double sm = 0.0;
        for (int kk = 0; kk < PK; kk++) { double e = exp(lg[kk]-mx); wr[kk] = e; sm += e; }
        double inv = 1.0 / sm;
        for (int kk = 0; kk < PK; kk++) wr[kk] *= inv;
        float bs = -1e30f; int kst = 0;
        for (int kk = 0; kk < PK; kk++) if (swf[kk] > bs) { bs = swf[kk]; kst = kk; }
        s_best = bs; s_kstar = kst;
    }
    __syncthreads();

    float r = 0.f, rc = 0.f;
    for (int kk = 0; kk < PK; kk++)
        kahan_add(r, rc, __fmul_rn((float)wr[kk], epi_vals[(size_t)(b*PK + kk)*PD + tid]));
    sred[tid] = (double)r * (double)r;
    __syncthreads();
    for (int s = 256; s >= 1; s >>= 1) { if (tid < s) sred[tid] += sred[tid+s]; __syncthreads(); }
    double rinv = 1.0 / sqrt(sred[0] * (1.0/512.0) + 1e-6);
    read_out[b*PD + tid] = (float)((double)r * rinv * (double)rms_read[tid]);
    __syncthreads();

    float ws = (float)s_ws; int kstar = s_kstar;

    for (int kk = warp; kk < PK; kk += 16) {
        float re = (kk == kstar) ? ws * 0.5f : 0.0f;
        const float* kp = epi_keys + (size_t)(b*PK + kk) * PD;
        const float* vp = epi_vals + (size_t)(b*PK + kk) * PD;
        float ss = 0.f;
        for (int d = lane; d < 512; d += 32) {
            float tk = (1.0f - re)*kp[d] + re*wkf[d];
            ss = fmaf(tk, tk, ss);
            vals_new[(size_t)(b*PK + kk)*PD + d] = (1.0f - re)*vp[d] + re*wvf[d];
        }
#pragma unroll
        for (int o = 16; o > 0; o >>= 1) ss += __shfl_xor_sync(0xffffffffu, ss, o);
        float ninv = (float)(1.0 / (sqrt((double)ss) + 1e-6));
        for (int d = lane; d < 512; d += 32) {
            float tk = (1.0f - re)*kp[d] + re*wkf[d];
            keys_new[(size_t)(b*PK + kk)*PD + d] = tk * ninv;
        }
    }

    if (tid < PK) {
        int kk = tid;
        float ww = (kk == kstar) ? 1.0f : 0.0f;
        age_new[b*PK + kk] = (epi_age[b*PK + kk] + 1.0f) * (1.0f - ww);
        float s0 = epi_str[b*PK + kk] * 0.995f;
        float snv = s0 + ww * ws * (1.0f - s0);
        sn_out[b*PK + kk] = fminf(fmaxf(snv, 0.001f), 1.0f);
    }

    {
        float nov = 1.0f - s_best;
        float hs = 0.f, hc = 0.f;
        for (int i = 0; i < 512; i++)
            kahan_add(hs, hc, __fmul_rn(qwf[i], Wg1[i*512 + tid]));
        kahan_add(hs, hc, __fmul_rn(ws,  Wg1[512*512 + tid]));
        kahan_add(hs, hc, __fmul_rn(nov, Wg1[513*512 + tid]));
        double hsum = (double)__fadd_rn(hs, bg1[tid]);
        double sil = hsum / (1.0 + exp(-hsum));
        sred[tid] = sil * (double)Wg2[tid];
    }
    __syncthreads();
    for (int s = 256; s >= 1; s >>= 1) { if (tid < s) sred[tid] += sred[tid+s]; __syncthreads(); }
    if (tid == 0) gate_out[b] = (float)(1.0 / (1.0 + exp(-(sred[0] + (double)bg2[0]))));
}

// ---------------- out += gate[b] * read[b, :] ----------------
__global__ void bcast_add_kernel(float* __restrict__ out,
                                 const float* __restrict__ read,
                                 const float* __restrict__ gate)
{
    size_t idx = (size_t)blockIdx.x * blockDim.x + threadIdx.x;
    int b = (int)(idx >> 18);
    int d = (int)(idx & 511);
    out[idx] += gate[b] * read[b*PD + d];
}

// ---------------- launch ----------------
extern "C" void kernel_launch(void* const* d_in, const int* in_sizes, int n_in,
                              void* d_out, int out_size)
{
    const float* x        = (const float*)d_in[0];
    const float* epi_keys = (const float*)d_in[1];
    const float* epi_vals = (const float*)d_in[2];
    const float* epi_age  = (const float*)d_in[3];
    const float* epi_str  = (const float*)d_in[4];
    const float* rms1     = (const float*)d_in[6];
    const float* rms_kv   = (const float*)d_in[7];
    const float* rms2     = (const float*)d_in[8];
    const float* rms_read = (const float*)d_in[9];
    const float* Wq = (const float*)d_in[10]; const float* bq = (const float*)d_in[11];
    const float* Wk = (const float*)d_in[12]; const float* bk = (const float*)d_in[13];
    const float* Wv = (const float*)d_in[14]; const float* bv = (const float*)d_in[15];
    const float* Wo = (const float*)d_in[16]; const float* bo = (const float*)d_in[17];
    const float* W1 = (const float*)d_in[18]; const float* W2 = (const float*)d_in[19];
    const float* Wwk = (const float*)d_in[20]; const float* bwk = (const float*)d_in[21];
    const float* Wwv = (const float*)d_in[22]; const float* bwv = (const float*)d_in[23];
    const float* Wws = (const float*)d_in[24]; const float* bws = (const float*)d_in[25];
    const float* Wg1 = (const float*)d_in[26]; const float* bg1 = (const float*)d_in[27];
    const float* Wg2 = (const float*)d_in[28]; const float* bg2 = (const float*)d_in[29];

    float *nx, *nkv, *q, *k, *v, *o, *h1, *nh1, *gv, *readb, *ropetab;
    double *qwin, *qpart;
    cudaGetSymbolAddress((void**)&nx,   g_nx);
    cudaGetSymbolAddress((void**)&nkv,  g_nkv);
    cudaGetSymbolAddress((void**)&q,    g_q);
    cudaGetSymbolAddress((void**)&k,    g_k);
    cudaGetSymbolAddress((void**)&v,    g_v);
    cudaGetSymbolAddress((void**)&o,    g_o);
    cudaGetSymbolAddress((void**)&h1,   g_h1);
    cudaGetSymbolAddress((void**)&nh1,  g_nh1);
    cudaGetSymbolAddress((void**)&gv,   g_gv);
    cudaGetSymbolAddress((void**)&qwin, g_qwin);
    cudaGetSymbolAddress((void**)&qpart,g_qpart);
    cudaGetSymbolAddress((void**)&readb,g_read);
    cudaGetSymbolAddress((void**)&ropetab, g_rope);

    float* out      = (float*)d_out;
    float* keys_new = out + (size_t)ROWS*PD;
    float* vals_new = keys_new + (size_t)PB*PK*PD;
    float* age_new  = vals_new + (size_t)PB*PK*PD;
    float* sn       = age_new + PB*PK;
    float* gate     = sn + PB*PK;

    cudaFuncSetAttribute(mma_gemm_kernel<true,false,true,false>,
                         cudaFuncAttributeMaxDynamicSharedMemorySize, GSMEM_BYTES);
    cudaFuncSetAttribute(mma_gemm_kernel<true,false,false,false>,
                         cudaFuncAttributeMaxDynamicSharedMemorySize, GSMEM_BYTES);
    cudaFuncSetAttribute(mma_gemm_kernel<true,true,false,false>,
                         cudaFuncAttributeMaxDynamicSharedMemorySize, GSMEM_BYTES);
    cudaFuncSetAttribute(mma_gemm_kernel<false,false,false,false>,
                         cudaFuncAttributeMaxDynamicSharedMemorySize, GSMEM_BYTES);
    cudaFuncSetAttribute(mma_gemm_kernel<false,true,false,true>,
                         cudaFuncAttributeMaxDynamicSharedMemorySize, GSMEM_BYTES);

    dim3 blk(256);
    dim3 pgrid(GEMM_GRID);

    rope_table_kernel<<<64, 256>>>(ropetab);
    rmsnorm_kernel<<<ROWS, 256>>>(x, rms1, nx, rms_kv, nkv);
    mma_gemm_kernel<true,false,true,false><<<pgrid, blk, GSMEM_BYTES>>>(
        nx,  nullptr, Wq, bq, nullptr, ropetab, q, ROWS, 512, 512, 512);
    mma_gemm_kernel<true,false,true,false><<<pgrid, blk, GSMEM_BYTES>>>(
        nkv, nullptr, Wk, bk, nullptr, ropetab, k, ROWS, 512, 512, 512);
    mma_gemm_kernel<true,false,false,false><<<pgrid, blk, GSMEM_BYTES>>>(
        nkv, nullptr, Wv, bv, nullptr, nullptr, v, ROWS, 512, 512, 512);
    attn_kernel<<<dim3(PT/128, PH, PB), 128>>>(q, k, v, o);
    mma_gemm_kernel<true,true,false,false><<<pgrid, blk, GSMEM_BYTES>>>(
        o, nullptr, Wo, bo, x, nullptr, h1, ROWS, 512, 512, 512);
    rmsnorm_kernel<<<ROWS, 256>>>(h1, rms2, nh1, nullptr, nullptr);
    mma_gemm_kernel<false,false,false,false><<<pgrid, blk, GSMEM_BYTES>>>(
        nh1, nullptr, W1, nullptr, nullptr, nullptr, gv, ROWS, 4096, 512, 512);
    mma_gemm_kernel<false,true,false,true><<<pgrid, blk, GSMEM_BYTES>>>(
        gv, gv + 2048, W2, nullptr, h1, nullptr, out, ROWS, 512, 2048, 4096);
    qwin_part_kernel<<<dim3(8, PB), 512>>>(out, qpart);
    qwin_reduce_kernel<<<PB, 512>>>(qpart, qwin);
    episodic_kernel<<<PB, 512>>>(epi_keys, epi_vals, epi_age, epi_str, rms_read,
                                 Wwk, bwk, Wwv, bwv, Wws, bws, Wg1, bg1, Wg2, bg2,
                                 qwin, readb, keys_new, vals_new, age_new, sn, gate);
    bcast_add_kernel<<<(ROWS*PD)/256, 256>>>(out, readb, gate);
}

// round 15
// speedup vs baseline: 1.0592x; 1.0095x over previous
#include <cuda_runtime.h>
#include <math.h>
#include <stdint.h>

// ---------------- problem constants ----------------
#define PB 32
#define PT 512
#define PD 512
#define PH 8
#define PK 64
#define PDH 64
#define ROWS (PB*PT)           // 16384

// ---------------- scratch (device globals; no allocation) ----------------
__device__ float  g_q   [ROWS*PD];
__device__ float  g_k   [ROWS*PD];
__device__ float  g_v   [ROWS*PD];
__device__ float  g_o   [ROWS*PD];
__device__ float  g_h1  [ROWS*PD];
__device__ float  g_gv  [ROWS*4096];
__device__ float  g_invx[ROWS];
__device__ float  g_invh[ROWS];
__device__ double g_qwin[PB*PD];
__device__ double g_qpart[PB*8*PD];
__device__ float  g_read[PB*PD];
__device__ float  g_rope[PT*32*2];     // cos/sin table [t][i][2]

// ---------------- tf32 split helpers ----------------
__device__ __forceinline__ void split_tf32u(float x, uint32_t &hi, uint32_t &lo) {
    asm("cvt.rna.tf32.f32 %0, %1;" : "=r"(hi) : "f"(x));
    lo = __float_as_uint(__fsub_rn(x, __uint_as_float(hi)));
}

__device__ __forceinline__ void mma_tf32(float4 &d,
    uint32_t a0, uint32_t a1, uint32_t a2, uint32_t a3,
    uint32_t b0, uint32_t b1)
{
    asm volatile(
        "mma.sync.aligned.m16n8k8.row.col.f32.tf32.tf32.f32 "
        "{%0,%1,%2,%3}, {%4,%5,%6,%7}, {%8,%9}, {%0,%1,%2,%3};"
        : "+f"(d.x), "+f"(d.y), "+f"(d.z), "+f"(d.w)
        : "r"(a0), "r"(a1), "r"(a2), "r"(a3), "r"(b0), "r"(b1));
}

__device__ __forceinline__ void cp_async16(uint32_t dst, const void* src) {
    asm volatile("cp.async.ca.shared.global [%0], [%1], 16;\n" :: "r"(dst), "l"(src));
}

// Kahan compensated add with IEEE intrinsics
__device__ __forceinline__ void kahan_add(float &s, float &c, float x) {
    float y = __fsub_rn(x, c);
    float t = __fadd_rn(s, y);
    c = __fsub_rn(__fsub_rn(t, s), y);
    s = t;
}

__device__ __forceinline__ float silu_mulf(float g, float vl) {
    return g / (1.0f + expf(-g)) * vl;
}

// ---------------- GEMM geometry (R12 proven optimum) ----------------
#define BK 16
#define A_LD 20
#define B_LD 136
#define A_PLANE (128*A_LD)
#define B_PLANE (BK*B_LD)
#define STAGE_FLOATS (A_PLANE + B_PLANE)
#define NSTAGE 3
#define GSMEM_BYTES (NSTAGE*STAGE_FLOATS*4)   // 56832 B
#define GEMM_GRID 296

// ---------------- 3xTF32 tensor-core GEMM: persistent, cp.async 3-stage ----------------
// ROPE: rotary in epilogue (q/k).  SILU: A = silu(g)*val on the fly (W2).
// RMS:  A = (A * invr[row]) * scal[kcol] on the fly (rmsnorm fusion).
template<bool BIAS, bool RES, bool ROPE, bool SILU, bool RMS>
__global__ void __launch_bounds__(256, 2) mma_gemm_kernel(
    const float* __restrict__ A, const float* __restrict__ A2,
    const float* __restrict__ Bm,
    const float* __restrict__ bias, const float* __restrict__ res,
    const float* __restrict__ rtab,
    const float* __restrict__ invr, const float* __restrict__ scal,
    float* __restrict__ C, int M, int N, int Kd, int lda)
{
    extern __shared__ float sm[];
    const uint32_t smem_u32 = (uint32_t)__cvta_generic_to_shared(sm);

    const int tid  = threadIdx.x;
    const int lane = tid & 31, warp = tid >> 5;
    const int wm = warp >> 1, wn = warp & 1;

    const int a_r = tid >> 1;
    const int a_c = (tid & 1) * 8;
    const int b_r = tid >> 4;
    const int b_c = (tid & 15) * 8;

    const int nk = Kd / BK;
    const int nrow = M >> 7;
    const int ntiles = nrow * (N >> 7);

    for (int tile = blockIdx.x; tile < ntiles; tile += GEMM_GRID) {
        const int row0 = (tile % nrow) << 7;
        const int col0 = (tile / nrow) << 7;

        float4 acc[2][8];
#pragma unroll
        for (int i = 0; i < 2; i++)
#pragma unroll
            for (int j = 0; j < 8; j++) acc[i][j] = make_float4(0.f, 0.f, 0.f, 0.f);

        auto issue_tile = [&](int it, int slot) {
            int k0 = it * BK;
            if (SILU) {
                size_t gi = (size_t)(row0 + a_r) * lda + k0 + a_c;
                float4 ga = *(const float4*)&A[gi];
                float4 gb = *(const float4*)&A[gi + 4];
                float4 va = *(const float4*)&A2[gi];
                float4 vb = *(const float4*)&A2[gi + 4];
                float4 u0 = make_float4(silu_mulf(ga.x, va.x), silu_mulf(ga.y, va.y),
                                        silu_mulf(ga.z, va.z), silu_mulf(ga.w, va.w));
                float4 u1 = make_float4(silu_mulf(gb.x, vb.x), silu_mulf(gb.y, vb.y),
                                        silu_mulf(gb.z, vb.z), silu_mulf(gb.w, vb.w));
                float* ap = sm + slot*STAGE_FLOATS + a_r*A_LD + a_c;
                *(float4*)(ap)     = u0;
                *(float4*)(ap + 4) = u1;
            } else if (RMS) {
                size_t gi = (size_t)(row0 + a_r) * lda + k0 + a_c;
                float4 xa = *(const float4*)&A[gi];
                float4 xb = *(const float4*)&A[gi + 4];
                float iv = invr[row0 + a_r];
                float4 sa = *(const float4*)&scal[k0 + a_c];
                float4 sb = *(const float4*)&scal[k0 + a_c + 4];
                // (x * inv) * s  -- same evaluation order as the old rmsnorm kernel
                float4 u0 = make_float4(
                    __fmul_rn(__fmul_rn(xa.x, iv), sa.x),
                    __fmul_rn(__fmul_rn(xa.y, iv), sa.y),
                    __fmul_rn(__fmul_rn(xa.z, iv), sa.z),
                    __fmul_rn(__fmul_rn(xa.w, iv), sa.w));
                float4 u1 = make_float4(
                    __fmul_rn(__fmul_rn(xb.x, iv), sb.x),
                    __fmul_rn(__fmul_rn(xb.y, iv), sb.y),
                    __fmul_rn(__fmul_rn(xb.z, iv), sb.z),
                    __fmul_rn(__fmul_rn(xb.w, iv), sb.w));
                float* ap = sm + slot*STAGE_FLOATS + a_r*A_LD + a_c;
                *(float4*)(ap)     = u0;
                *(float4*)(ap + 4) = u1;
            } else {
                uint32_t abase = smem_u32 + (slot*STAGE_FLOATS + a_r*A_LD + a_c) * 4;
                const float* ag = &A[(size_t)(row0 + a_r) * lda + k0 + a_c];
                cp_async16(abase,      ag);
                cp_async16(abase + 16, ag + 4);
            }
            uint32_t bbase = smem_u32 + (slot*STAGE_FLOATS + A_PLANE + b_r*B_LD + b_c) * 4;
            const float* bg = &Bm[(size_t)(k0 + b_r) * N + col0 + b_c];
            cp_async16(bbase,      bg);
            cp_async16(bbase + 16, bg + 4);
            asm volatile("cp.async.commit_group;\n");
        };

        issue_tile(0, 0);
        issue_tile(1, 1);

        for (int it = 0; it < nk; it++) {
            if (it + 1 < nk) { asm volatile("cp.async.wait_group 1;\n"); }
            else             { asm volatile("cp.async.wait_group 0;\n"); }
            __syncthreads();
            if (it + 2 < nk) issue_tile(it + 2, (it + 2) % NSTAGE);

            const float* as = sm + (it % NSTAGE) * STAGE_FLOATS;
            const float* bs = as + A_PLANE;
#pragma unroll
            for (int kk = 0; kk < 2; kk++) {
                const int kb = kk * 8;
                uint32_t ahi[2][4], alo[2][4], bhi[8][2], blo[8][2];
#pragma unroll
                for (int tm = 0; tm < 2; tm++) {
                    int r0 = (wm*32 + tm*16 + (lane >> 2)) * A_LD;
                    int c0 = kb + (lane & 3);
                    split_tf32u(as[r0          + c0    ], ahi[tm][0], alo[tm][0]);
                    split_tf32u(as[r0 + 8*A_LD + c0    ], ahi[tm][1], alo[tm][1]);
                    split_tf32u(as[r0          + c0 + 4], ahi[tm][2], alo[tm][2]);
                    split_tf32u(as[r0 + 8*A_LD + c0 + 4], ahi[tm][3], alo[tm][3]);
                }
#pragma unroll
                for (int tn = 0; tn < 8; tn++) {
                    int c = wn*64 + tn*8 + (lane >> 2);
                    int r0 = (kb + (lane & 3)) * B_LD;
                    split_tf32u(bs[r0          + c], bhi[tn][0], blo[tn][0]);
                    split_tf32u(bs[r0 + 4*B_LD + c], bhi[tn][1], blo[tn][1]);
                }
#pragma unroll
                for (int tm = 0; tm < 2; tm++)
#pragma unroll
                    for (int tn = 0; tn < 8; tn++)
                        mma_tf32(acc[tm][tn], ahi[tm][0], ahi[tm][1], ahi[tm][2], ahi[tm][3],
                                 bhi[tn][0], bhi[tn][1]);
#pragma unroll
                for (int tm = 0; tm < 2; tm++)
#pragma unroll
                    for (int tn = 0; tn < 8; tn++)
                        mma_tf32(acc[tm][tn], ahi[tm][0], ahi[tm][1], ahi[tm][2], ahi[tm][3],
                                 blo[tn][0], blo[tn][1]);
#pragma unroll
                for (int tm = 0; tm < 2; tm++)
#pragma unroll
                    for (int tn = 0; tn < 8; tn++)
                        mma_tf32(acc[tm][tn], alo[tm][0], alo[tm][1], alo[tm][2], alo[tm][3],
                                 bhi[tn][0], bhi[tn][1]);
            }
        }

        // epilogue
#pragma unroll
        for (int tm = 0; tm < 2; tm++) {
            int r0 = row0 + wm*32 + tm*16 + (lane >> 2);
#pragma unroll
            for (int tn = 0; tn < 8; tn++) {
                int c0 = col0 + wn*64 + tn*8 + 2*(lane & 3);
                float2 v0 = make_float2(acc[tm][tn].x, acc[tm][tn].y);
                float2 v1 = make_float2(acc[tm][tn].z, acc[tm][tn].w);
                if (BIAS) {
                    v0.x += bias[c0]; v0.y += bias[c0+1];
                    v1.x += bias[c0]; v1.y += bias[c0+1];
                }
                if (RES) {
                    float2 r0v = *(const float2*)&res[(size_t)r0 * N + c0];
                    float2 r1v = *(const float2*)&res[(size_t)(r0+8) * N + c0];
                    v0.x += r0v.x; v0.y += r0v.y;
                    v1.x += r1v.x; v1.y += r1v.y;
                }
                if (ROPE) {
                    int i = (c0 & 63) >> 1;
                    int t0 = r0 & (PT - 1);
                    int t1 = (r0 + 8) & (PT - 1);
                    float2 cs0 = *(const float2*)&rtab[2*(t0*32 + i)];
                    float2 cs1 = *(const float2*)&rtab[2*(t1*32 + i)];
                    float x0 = v0.x, x1 = v0.y;
                    v0.x = x0*cs0.x - x1*cs0.y;
                    v0.y = x0*cs0.y + x1*cs0.x;
                    x0 = v1.x; x1 = v1.y;
                    v1.x = x0*cs1.x - x1*cs1.y;
                    v1.y = x0*cs1.y + x1*cs1.x;
                }
                *(float2*)&C[(size_t)r0 * N + c0]     = v0;
                *(float2*)&C[(size_t)(r0+8) * N + c0] = v1;
            }
        }
        __syncthreads();
    }
}

// ---------------- inverse RMS norm per row (reduction order == old rmsnorm) ----
__global__ void invnorm_kernel(const float* __restrict__ x, float* __restrict__ inv)
{
    int row = blockIdx.x, tid = threadIdx.x;   // 256 threads
    const float* xr = x + (size_t)row * PD;
    float v0 = xr[tid], v1 = xr[tid + 256];
    __shared__ float sred[256];
    sred[tid] = v0*v0 + v1*v1;
    __syncthreads();
    for (int s = 128; s >= 1; s >>= 1) {
        if (tid < s) sred[tid] += sred[tid + s];
        __syncthreads();
    }
    if (tid == 0) inv[row] = rsqrtf(sred[0] * (1.0f/512.0f) + 1e-6f);
}

// ---------------- RoPE table ----------------
__global__ void rope_table_kernel(float* __restrict__ tab)
{
    int idx = blockIdx.x * 256 + threadIdx.x;
    int t = idx >> 5, i = idx & 31;
    double freq = exp(-((double)(2*i) / 64.0) * 9.210340371976184);
    double ang = (double)t * freq;
    tab[2*idx    ] = (float)cos(ang);
    tab[2*idx + 1] = (float)sin(ang);
}

// ---------------- causal attention: R12 proven (32-key tiles, float4 reads) ----
__global__ void __launch_bounds__(128) attn_kernel(
    const float* __restrict__ q, const float* __restrict__ k,
    const float* __restrict__ v, float* __restrict__ o)
{
    const int BS = 32;
    __shared__ float Ks[BS][64];
    __shared__ float Vs[BS][64];
    int t = blockIdx.x * 128 + threadIdx.x;
    int h = blockIdx.y, b = blockIdx.z;
    const float* qrow = q + ((size_t)(b*PT + t) * PD + h*PDH);
    float qreg[64];
#pragma unroll
    for (int i = 0; i < 64; i++) qreg[i] = qrow[i];
    float m = -1e30f, l = 0.0f;
    float acc[64];
#pragma unroll
    for (int i = 0; i < 64; i++) acc[i] = 0.0f;

    int send = blockIdx.x * 128 + 128;
    for (int s0 = 0; s0 < send; s0 += BS) {
        __syncthreads();
        for (int i = threadIdx.x; i < BS*16; i += 128) {
            int rr = i >> 4; int cc = (i & 15) << 2;
            size_t goff = (size_t)(b*PT + s0 + rr) * PD + h*PDH + cc;
            *(float4*)&Ks[rr][cc] = *(const float4*)&k[goff];
            *(float4*)&Vs[rr][cc] = *(const float4*)&v[goff];
        }
        __syncthreads();
        int nval = t - s0 + 1;
        if (nval > BS) nval = BS;
        if (nval > 0) {
            float sc[BS];
            float tm = -1e30f;
#pragma unroll
            for (int j = 0; j < BS; j++) {
                float s = 0.0f;
#pragma unroll
                for (int d4 = 0; d4 < 16; d4++) {
                    float4 kv = *(const float4*)&Ks[j][d4*4];
                    s = fmaf(qreg[4*d4+0], kv.x, s);
                    s = fmaf(qreg[4*d4+1], kv.y, s);
                    s = fmaf(qreg[4*d4+2], kv.z, s);
                    s = fmaf(qreg[4*d4+3], kv.w, s);
                }
                s *= 0.125f;
                sc[j] = (j < nval) ? s : -1e30f;
                tm = fmaxf(tm, sc[j]);
            }
            float nm = fmaxf(m, tm);
            float csc = expf(m - nm);
            l *= csc;
#pragma unroll
            for (int d = 0; d < 64; d++) acc[d] *= csc;
#pragma unroll
            for (int j = 0; j < BS; j++) {
                float p = expf(sc[j] - nm);
                l += p;
#pragma unroll
                for (int d4 = 0; d4 < 16; d4++) {
                    float4 vv = *(const float4*)&Vs[j][d4*4];
                    acc[4*d4+0] = fmaf(p, vv.x, acc[4*d4+0]);
                    acc[4*d4+1] = fmaf(p, vv.y, acc[4*d4+1]);
                    acc[4*d4+2] = fmaf(p, vv.z, acc[4*d4+2]);
                    acc[4*d4+3] = fmaf(p, vv.w, acc[4*d4+3]);
                }
            }
            m = nm;
        }
    }
    float inv = 1.0f / l;
    float* orow = o + ((size_t)(b*PT + t) * PD + h*PDH);
#pragma unroll
    for (int i = 0; i < 64; i++) orow[i] = acc[i] * inv;
}

// ---------------- mean over T: two-stage f64 ----------------
__global__ void qwin_part_kernel(const float* __restrict__ h2, double* __restrict__ part)
{
    int b = blockIdx.y, chunk = blockIdx.x, d = threadIdx.x;
    double s = 0.0;
    int t0 = chunk * 64;
    for (int t = t0; t < t0 + 64; t++)
        s += (double)h2[((size_t)(b*PT + t)) * PD + d];
    part[((size_t)b*8 + chunk) * PD + d] = s;
}
__global__ void qwin_reduce_kernel(const double* __restrict__ part, double* __restrict__ qwin)
{
    int b = blockIdx.x, d = threadIdx.x;
    double s = 0.0;
    for (int c = 0; c < 8; c++) s += part[((size_t)b*8 + c) * PD + d];
    qwin[b*PD + d] = s * (1.0 / (double)PT);
}

// ---------------- episodic memory: Kahan-f32 heavy math, f64 scalars ----------------
__global__ void __launch_bounds__(512) episodic_kernel(
    const float* __restrict__ epi_keys, const float* __restrict__ epi_vals,
    const float* __restrict__ epi_age,  const float* __restrict__ epi_str,
    const float* __restrict__ rms_read,
    const float* __restrict__ Wwk, const float* __restrict__ bwk,
    const float* __restrict__ Wwv, const float* __restrict__ bwv,
    const float* __restrict__ Wws, const float* __restrict__ bws,
    const float* __restrict__ Wg1, const float* __restrict__ bg1,
    const float* __restrict__ Wg2, const float* __restrict__ bg2,
    const double* __restrict__ qwin,
    float* __restrict__ read_out,
    float* __restrict__ keys_new, float* __restrict__ vals_new,
    float* __restrict__ age_new,  float* __restrict__ sn_out,
    float* __restrict__ gate_out)
{
    int b = blockIdx.x;
    int tid = threadIdx.x;
    int warp = tid >> 5, lane = tid & 31;
    __shared__ float  qwf[512], wkf[512], wvf[512];
    __shared__ double sred[512];
    __shared__ double lg[64], wr[64];
    __shared__ float  swf[64];
    __shared__ double s_qninv, s_ws, s_wkinv;
    __shared__ float  s_best;
    __shared__ int    s_kstar;

    double qwd = qwin[b*PD + tid];
    qwf[tid] = (float)qwd;
    __syncthreads();

    sred[tid] = qwd*qwd;
    __syncthreads();
    for (int s = 256; s >= 1; s >>= 1) { if (tid < s) sred[tid] += sred[tid+s]; __syncthreads(); }
    if (tid == 0) s_qninv = 1.0 / (sqrt(sred[0]) + 1e-6);
    __syncthreads();

    {
        float a1 = 0.f, c1 = 0.f, a2 = 0.f, c2 = 0.f;
        for (int i = 0; i < 512; i++) {
            float qv = qwf[i];
            kahan_add(a1, c1, __fmul_rn(qv, Wwk[i*512 + tid]));
            kahan_add(a2, c2, __fmul_rn(qv, Wwv[i*512 + tid]));
        }
        wkf[tid] = __fadd_rn(a1, bwk[tid]);
        wvf[tid] = __fadd_rn(a2, bwv[tid]);
    }

    sred[tid] = qwd * (double)Wws[tid];
    __syncthreads();
    for (int s = 256; s >= 1; s >>= 1) { if (tid < s) sred[tid] += sred[tid+s]; __syncthreads(); }
    if (tid == 0) s_ws = 1.0 / (1.0 + exp(-(sred[0] + (double)bws[0])));
    __syncthreads();

    sred[tid] = (double)wkf[tid] * (double)wkf[tid];
    __syncthreads();
    for (int s = 256; s >= 1; s >>= 1) { if (tid < s) sred[tid] += sred[tid+s]; __syncthreads(); }
    if (tid == 0) s_wkinv = 1.0 / (sqrt(sred[0]) + 1e-6);
    __syncthreads();

    for (int kk = warp; kk < PK; kk += 16) {
        const float* kp = epi_keys + (size_t)(b*PK + kk) * PD;
        float ss = 0.f, ssc = 0.f, dq = 0.f, dqc = 0.f, dw = 0.f, dwc = 0.f;
        for (int d = lane; d < 512; d += 32) {
            float kv = kp[d];
            kahan_add(ss, ssc, __fmul_rn(kv, kv));
            kahan_add(dq, dqc, __fmul_rn(kv, qwf[d]));
            kahan_add(dw, dwc, __fmul_rn(kv, wkf[d]));
        }
#pragma unroll
        for (int o = 16; o > 0; o >>= 1) {
            ss += __shfl_xor_sync(0xffffffffu, ss, o);
            dq += __shfl_xor_sync(0xffffffffu, dq, o);
            dw += __shfl_xor_sync(0xffffffffu, dw, o);
        }
        if (lane == 0) {
            double kninv = 1.0 / (sqrt((double)ss) + 1e-6);
            double simr  = (double)dq * kninv * s_qninv;
            double st    = (double)epi_str[b*PK + kk];
            double stc   = fmin(fmax(st, 0.001), 1e9);
            lg[kk] = simr + 0.5*log(stc) - 0.02*(double)epi_age[b*PK + kk]
                   + ((st > 0.001) ? 0.0 : -1000.0);
            swf[kk] = (float)((double)dw * kninv * s_wkinv);
        }
    }
    __syncthreads();

    if (tid == 0) {
        double mx = -1e300;
        for (int kk = 0; kk < PK; kk++) mx = fmax(mx, lg[kk]);
        double sm = 0.0;
        for (int kk = 0; kk < PK; kk++) { double e = exp(lg[kk]-mx); wr[kk] = e; sm += e; }
        double inv = 1.0 / sm;
        for (int kk = 0; kk < PK; kk++) wr[kk] *= inv;
        float bs = -1e30f; int kst = 0;
        for (int kk = 0; kk < PK; kk++) if (swf[kk] > bs) { bs = swf[kk]; kst = kk; }
        s_best = bs; s_kstar = kst;
    }
    __syncthreads();

    float r = 0.f, rc = 0.f;
    for (int kk = 0; kk < PK; kk++)
        kahan_add(r, rc, __fmul_rn((float)wr[kk], epi_vals[(size_t)(b*PK + kk)*PD + tid]));
    sred[tid] = (double)r * (double)r;
    __syncthreads();
    for (int s = 256; s >= 1; s >>= 1) { if (tid < s) sred[tid] += sred[tid+s]; __syncthreads(); }
    double rinv = 1.0 / sqrt(sred[0] * (1.0/512.0) + 1e-6);
    read_out[b*PD + tid] = (float)((double)r * rinv * (double)rms_read[tid]);
    __syncthreads();

    float ws = (float)s_ws; int kstar = s_kstar;

    for (int kk = warp; kk < PK; kk += 16) {
        float re = (kk == kstar) ? ws * 0.5f : 0.0f;
        const float* kp = epi_keys + (size_t)(b*PK + kk) * PD;
        const float* vp = epi_vals + (size_t)(b*PK + kk) * PD;
        float ss = 0.f;
        for (int d = lane; d < 512; d += 32) {
            float tk = (1.0f - re)*kp[d] + re*wkf[d];
            ss = fmaf(tk, tk, ss);
            vals_new[(size_t)(b*PK + kk)*PD + d] = (1.0f - re)*vp[d] + re*wvf[d];
        }
#pragma unroll
        for (int o = 16; o > 0; o >>= 1) ss += __shfl_xor_sync(0xffffffffu, ss, o);
        float ninv = (float)(1.0 / (sqrt((double)ss) + 1e-6));
        for (int d = lane; d < 512; d += 32) {
            float tk = (1.0f - re)*kp[d] + re*wkf[d];
            keys_new[(size_t)(b*PK + kk)*PD + d] = tk * ninv;
        }
    }

    if (tid < PK) {
        int kk = tid;
        float ww = (kk == kstar) ? 1.0f : 0.0f;
        age_new[b*PK + kk] = (epi_age[b*PK + kk] + 1.0f) * (1.0f - ww);
        float s0 = epi_str[b*PK + kk] * 0.995f;
        float snv = s0 + ww * ws * (1.0f - s0);
        sn_out[b*PK + kk] = fminf(fmaxf(snv, 0.001f), 1.0f);
    }

    {
        float nov = 1.0f - s_best;
        float hs = 0.f, hc = 0.f;
        for (int i = 0; i < 512; i++)
            kahan_add(hs, hc, __fmul_rn(qwf[i], Wg1[i*512 + tid]));
        kahan_add(hs, hc, __fmul_rn(ws,  Wg1[512*512 + tid]));
        kahan_add(hs, hc, __fmul_rn(nov, Wg1[513*512 + tid]));
        double hsum = (double)__fadd_rn(hs, bg1[tid]);
        double sil = hsum / (1.0 + exp(-hsum));
        sred[tid] = sil * (double)Wg2[tid];
    }
    __syncthreads();
    for (int s = 256; s >= 1; s >>= 1) { if (tid < s) sred[tid] += sred[tid+s]; __syncthreads(); }
    if (tid == 0) gate_out[b] = (float)(1.0 / (1.0 + exp(-(sred[0] + (double)bg2[0]))));
}

// ---------------- out += gate[b] * read[b, :] ----------------
__global__ void bcast_add_kernel(float* __restrict__ out,
                                 const float* __restrict__ read,
                                 const float* __restrict__ gate)
{
    size_t idx = (size_t)blockIdx.x * blockDim.x + threadIdx.x;
    int b = (int)(idx >> 18);
    int d = (int)(idx & 511);
    out[idx] += gate[b] * read[b*PD + d];
}

// ---------------- launch ----------------
extern "C" void kernel_launch(void* const* d_in, const int* in_sizes, int n_in,
                              void* d_out, int out_size)
{
    const float* x        = (const float*)d_in[0];
    const float* epi_keys = (const float*)d_in[1];
    const float* epi_vals = (const float*)d_in[2];
    const float* epi_age  = (const float*)d_in[3];
    const float* epi_str  = (const float*)d_in[4];
    const float* rms1     = (const float*)d_in[6];
    const float* rms_kv   = (const float*)d_in[7];
    const float* rms2     = (const float*)d_in[8];
    const float* rms_read = (const float*)d_in[9];
    const float* Wq = (const float*)d_in[10]; const float* bq = (const float*)d_in[11];
    const float* Wk = (const float*)d_in[12]; const float* bk = (const float*)d_in[13];
    const float* Wv = (const float*)d_in[14]; const float* bv = (const float*)d_in[15];
    const float* Wo = (const float*)d_in[16]; const float* bo = (const float*)d_in[17];
    const float* W1 = (const float*)d_in[18]; const float* W2 = (const float*)d_in[19];
    const float* Wwk = (const float*)d_in[20]; const float* bwk = (const float*)d_in[21];
    const float* Wwv = (const float*)d_in[22]; const float* bwv = (const float*)d_in[23];
    const float* Wws = (const float*)d_in[24]; const float* bws = (const float*)d_in[25];
    const float* Wg1 = (const float*)d_in[26]; const float* bg1 = (const float*)d_in[27];
    const float* Wg2 = (const float*)d_in[28]; const float* bg2 = (const float*)d_in[29];

    float *q, *k, *v, *o, *h1, *gv, *readb, *ropetab, *invx, *invh;
    double *qwin, *qpart;
    cudaGetSymbolAddress((void**)&q,    g_q);
    cudaGetSymbolAddress((void**)&k,    g_k);
    cudaGetSymbolAddress((void**)&v,    g_v);
    cudaGetSymbolAddress((void**)&o,    g_o);
    cudaGetSymbolAddress((void**)&h1,   g_h1);
    cudaGetSymbolAddress((void**)&gv,   g_gv);
    cudaGetSymbolAddress((void**)&invx, g_invx);
    cudaGetSymbolAddress((void**)&invh, g_invh);
    cudaGetSymbolAddress((void**)&qwin, g_qwin);
    cudaGetSymbolAddress((void**)&qpart,g_qpart);
    cudaGetSymbolAddress((void**)&readb,g_read);
    cudaGetSymbolAddress((void**)&ropetab, g_rope);

    float* out      = (float*)d_out;
    float* keys_new = out + (size_t)ROWS*PD;
    float* vals_new = keys_new + (size_t)PB*PK*PD;
    float* age_new  = vals_new + (size_t)PB*PK*PD;
    float* sn       = age_new + PB*PK;
    float* gate     = sn + PB*PK;

    cudaFuncSetAttribute(mma_gemm_kernel<true,false,true,false,true>,
                         cudaFuncAttributeMaxDynamicSharedMemorySize, GSMEM_BYTES);
    cudaFuncSetAttribute(mma_gemm_kernel<true,false,false,false,true>,
                         cudaFuncAttributeMaxDynamicSharedMemorySize, GSMEM_BYTES);
    cudaFuncSetAttribute(mma_gemm_kernel<true,true,false,false,false>,
                         cudaFuncAttributeMaxDynamicSharedMemorySize, GSMEM_BYTES);
    cudaFuncSetAttribute(mma_gemm_kernel<false,false,false,false,true>,
                         cudaFuncAttributeMaxDynamicSharedMemorySize, GSMEM_BYTES);
    cudaFuncSetAttribute(mma_gemm_kernel<false,true,false,true,false>,
                         cudaFuncAttributeMaxDynamicSharedMemorySize, GSMEM_BYTES);

    dim3 blk(256);
    dim3 pgrid(GEMM_GRID);

    rope_table_kernel<<<64, 256>>>(ropetab);
    invnorm_kernel<<<ROWS, 256>>>(x, invx);
    // Q/K/V with fused RMS A-stager (Q/K also fuse RoPE epilogue)
    mma_gemm_kernel<true,false,true,false,true><<<pgrid, blk, GSMEM_BYTES>>>(
        x, nullptr, Wq, bq, nullptr, ropetab, invx, rms1,   q, ROWS, 512, 512, 512);
    mma_gemm_kernel<true,false,true,false,true><<<pgrid, blk, GSMEM_BYTES>>>(
        x, nullptr, Wk, bk, nullptr, ropetab, invx, rms_kv, k, ROWS, 512, 512, 512);
    mma_gemm_kernel<true,false,false,false,true><<<pgrid, blk, GSMEM_BYTES>>>(
        x, nullptr, Wv, bv, nullptr, nullptr, invx, rms_kv, v, ROWS, 512, 512, 512);
    attn_kernel<<<dim3(PT/128, PH, PB), 128>>>(q, k, v, o);
    mma_gemm_kernel<true,true,false,false,false><<<pgrid, blk, GSMEM_BYTES>>>(
        o, nullptr, Wo, bo, x, nullptr, nullptr, nullptr, h1, ROWS, 512, 512, 512);
    invnorm_kernel<<<ROWS, 256>>>(h1, invh);
    // W1 with fused RMS A-stager (reads h1 directly)
    mma_gemm_kernel<false,false,false,false,true><<<pgrid, blk, GSMEM_BYTES>>>(
        h1, nullptr, W1, nullptr, nullptr, nullptr, invh, rms2, gv, ROWS, 4096, 512, 512);
    // h2 = h1 + silu(g)*val @ W2
    mma_gemm_kernel<false,true,false,true,false><<<pgrid, blk, GSMEM_BYTES>>>(
        gv, gv + 2048, W2, nullptr, h1, nullptr, nullptr, nullptr, out, ROWS, 512, 2048, 4096);
    qwin_part_kernel<<<dim3(8, PB), 512>>>(out, qpart);
    qwin_reduce_kernel<<<PB, 512>>>(qpart, qwin);
    episodic_kernel<<<PB, 512>>>(epi_keys, epi_vals, epi_age, epi_str, rms_read,
                                 Wwk, bwk, Wwv, bwv, Wws, bws, Wg1, bg1, Wg2, bg2,
                                 qwin, readb, keys_new, vals_new, age_new, sn, gate);
    bcast_add_kernel<<<(ROWS*PD)/256, 256>>>(out, readb, gate);
}

// round 16
// speedup vs baseline: 1.1249x; 1.0620x over previous
#include <cuda_runtime.h>
#include <math.h>
#include <stdint.h>

// ---------------- problem constants ----------------
#define PB 32
#define PT 512
#define PD 512
#define PH 8
#define PK 64
#define PDH 64
#define ROWS (PB*PT)           // 16384

// ---------------- scratch (device globals; no allocation) ----------------
__device__ float  g_nx  [ROWS*PD];
__device__ float  g_nkv [ROWS*PD];
__device__ float  g_q   [ROWS*PD];
__device__ float  g_k   [ROWS*PD];
__device__ float  g_v   [ROWS*PD];
__device__ float  g_o   [ROWS*PD];
__device__ float  g_h1  [ROWS*PD];
__device__ float  g_nh1 [ROWS*PD];
__device__ float  g_gv  [ROWS*4096];
__device__ double g_qwin[PB*PD];
__device__ double g_qpart[PB*8*PD];
__device__ float  g_read[PB*PD];
__device__ float  g_rope[PT*32*2];     // cos/sin table [t][i][2]

// ---------------- tf32 split helpers ----------------
__device__ __forceinline__ void split_tf32u(float x, uint32_t &hi, uint32_t &lo) {
    asm("cvt.rna.tf32.f32 %0, %1;" : "=r"(hi) : "f"(x));
    lo = __float_as_uint(__fsub_rn(x, __uint_as_float(hi)));
}

__device__ __forceinline__ void mma_tf32(float4 &d,
    uint32_t a0, uint32_t a1, uint32_t a2, uint32_t a3,
    uint32_t b0, uint32_t b1)
{
    asm volatile(
        "mma.sync.aligned.m16n8k8.row.col.f32.tf32.tf32.f32 "
        "{%0,%1,%2,%3}, {%4,%5,%6,%7}, {%8,%9}, {%0,%1,%2,%3};"
        : "+f"(d.x), "+f"(d.y), "+f"(d.z), "+f"(d.w)
        : "r"(a0), "r"(a1), "r"(a2), "r"(a3), "r"(b0), "r"(b1));
}

__device__ __forceinline__ void cp_async16(uint32_t dst, const void* src) {
    asm volatile("cp.async.ca.shared.global [%0], [%1], 16;\n" :: "r"(dst), "l"(src));
}

// Kahan compensated add with IEEE intrinsics
__device__ __forceinline__ void kahan_add(float &s, float &c, float x) {
    float y = __fsub_rn(x, c);
    float t = __fadd_rn(s, y);
    c = __fsub_rn(__fsub_rn(t, s), y);
    s = t;
}

__device__ __forceinline__ float silu_mulf(float g, float vl) {
    return g / (1.0f + expf(-g)) * vl;
}

// ---------------- GEMM geometry (R12 tile, 4-stage ring) ----------------
#define BK 16
#define A_LD 20
#define B_LD 136
#define A_PLANE (128*A_LD)
#define B_PLANE (BK*B_LD)
#define STAGE_FLOATS (A_PLANE + B_PLANE)
#define NSTAGE 4
#define GSMEM_BYTES (NSTAGE*STAGE_FLOATS*4)   // 75776 B
#define GEMM_GRID 296

// ---------------- 3xTF32 tensor-core GEMM: persistent, cp.async 4-stage ----------------
template<bool BIAS, bool RES, bool ROPE, bool SILU>
__global__ void __launch_bounds__(256, 2) mma_gemm_kernel(
    const float* __restrict__ A, const float* __restrict__ A2,
    const float* __restrict__ Bm,
    const float* __restrict__ bias, const float* __restrict__ res,
    const float* __restrict__ rtab,
    float* __restrict__ C, int M, int N, int Kd, int lda)
{
    extern __shared__ float sm[];
    const uint32_t smem_u32 = (uint32_t)__cvta_generic_to_shared(sm);

    const int tid  = threadIdx.x;
    const int lane = tid & 31, warp = tid >> 5;
    const int wm = warp >> 1, wn = warp & 1;

    const int a_r = tid >> 1;
    const int a_c = (tid & 1) * 8;
    const int b_r = tid >> 4;
    const int b_c = (tid & 15) * 8;

    const int nk = Kd / BK;
    const int nrow = M >> 7;
    const int ntiles = nrow * (N >> 7);

    for (int tile = blockIdx.x; tile < ntiles; tile += GEMM_GRID) {
        const int row0 = (tile % nrow) << 7;
        const int col0 = (tile / nrow) << 7;

        float4 acc[2][8];
#pragma unroll
        for (int i = 0; i < 2; i++)
#pragma unroll
            for (int j = 0; j < 8; j++) acc[i][j] = make_float4(0.f, 0.f, 0.f, 0.f);

        auto issue_tile = [&](int it, int slot) {
            int k0 = it * BK;
            if (SILU) {
                size_t gi = (size_t)(row0 + a_r) * lda + k0 + a_c;
                float4 ga = *(const float4*)&A[gi];
                float4 gb = *(const float4*)&A[gi + 4];
                float4 va = *(const float4*)&A2[gi];
                float4 vb = *(const float4*)&A2[gi + 4];
                float4 u0 = make_float4(silu_mulf(ga.x, va.x), silu_mulf(ga.y, va.y),
                                        silu_mulf(ga.z, va.z), silu_mulf(ga.w, va.w));
                float4 u1 = make_float4(silu_mulf(gb.x, vb.x), silu_mulf(gb.y, vb.y),
                                        silu_mulf(gb.z, vb.z), silu_mulf(gb.w, vb.w));
                float* ap = sm + slot*STAGE_FLOATS + a_r*A_LD + a_c;
                *(float4*)(ap)     = u0;
                *(float4*)(ap + 4) = u1;
            } else {
                uint32_t abase = smem_u32 + (slot*STAGE_FLOATS + a_r*A_LD + a_c) * 4;
                const float* ag = &A[(size_t)(row0 + a_r) * lda + k0 + a_c];
                cp_async16(abase,      ag);
                cp_async16(abase + 16, ag + 4);
            }
            uint32_t bbase = smem_u32 + (slot*STAGE_FLOATS + A_PLANE + b_r*B_LD + b_c) * 4;
            const float* bg = &Bm[(size_t)(k0 + b_r) * N + col0 + b_c];
            cp_async16(bbase,      bg);
            cp_async16(bbase + 16, bg + 4);
            asm volatile("cp.async.commit_group;\n");
        };

        issue_tile(0, 0);
        issue_tile(1, 1);
        issue_tile(2, 2);

        for (int it = 0; it < nk; it++) {
            int rem = nk - 1 - it;                 // stages still to consume after this one
            if (rem >= 2)      { asm volatile("cp.async.wait_group 2;\n"); }
            else if (rem == 1) { asm volatile("cp.async.wait_group 1;\n"); }
            else               { asm volatile("cp.async.wait_group 0;\n"); }
            __syncthreads();
            if (it + 3 < nk) issue_tile(it + 3, (it + 3) % NSTAGE);

            const float* as = sm + (it % NSTAGE) * STAGE_FLOATS;
            const float* bs = as + A_PLANE;
#pragma unroll
            for (int kk = 0; kk < 2; kk++) {
                const int kb = kk * 8;
                uint32_t ahi[2][4], alo[2][4], bhi[8][2], blo[8][2];
#pragma unroll
                for (int tm = 0; tm < 2; tm++) {
                    int r0 = (wm*32 + tm*16 + (lane >> 2)) * A_LD;
                    int c0 = kb + (lane & 3);
                    split_tf32u(as[r0          + c0    ], ahi[tm][0], alo[tm][0]);
                    split_tf32u(as[r0 + 8*A_LD + c0    ], ahi[tm][1], alo[tm][1]);
                    split_tf32u(as[r0          + c0 + 4], ahi[tm][2], alo[tm][2]);
                    split_tf32u(as[r0 + 8*A_LD + c0 + 4], ahi[tm][3], alo[tm][3]);
                }
#pragma unroll
                for (int tn = 0; tn < 8; tn++) {
                    int c = wn*64 + tn*8 + (lane >> 2);
                    int r0 = (kb + (lane & 3)) * B_LD;
                    split_tf32u(bs[r0          + c], bhi[tn][0], blo[tn][0]);
                    split_tf32u(bs[r0 + 4*B_LD + c], bhi[tn][1], blo[tn][1]);
                }
#pragma unroll
                for (int tm = 0; tm < 2; tm++)
#pragma unroll
                    for (int tn = 0; tn < 8; tn++)
                        mma_tf32(acc[tm][tn], ahi[tm][0], ahi[tm][1], ahi[tm][2], ahi[tm][3],
                                 bhi[tn][0], bhi[tn][1]);
#pragma unroll
                for (int tm = 0; tm < 2; tm++)
#pragma unroll
                    for (int tn = 0; tn < 8; tn++)
                        mma_tf32(acc[tm][tn], ahi[tm][0], ahi[tm][1], ahi[tm][2], ahi[tm][3],
                                 blo[tn][0], blo[tn][1]);
#pragma unroll
                for (int tm = 0; tm < 2; tm++)
#pragma unroll
                    for (int tn = 0; tn < 8; tn++)
                        mma_tf32(acc[tm][tn], alo[tm][0], alo[tm][1], alo[tm][2], alo[tm][3],
                                 bhi[tn][0], bhi[tn][1]);
            }
        }

        // epilogue
#pragma unroll
        for (int tm = 0; tm < 2; tm++) {
            int r0 = row0 + wm*32 + tm*16 + (lane >> 2);
#pragma unroll
            for (int tn = 0; tn < 8; tn++) {
                int c0 = col0 + wn*64 + tn*8 + 2*(lane & 3);
                float2 v0 = make_float2(acc[tm][tn].x, acc[tm][tn].y);
                float2 v1 = make_float2(acc[tm][tn].z, acc[tm][tn].w);
                if (BIAS) {
                    v0.x += bias[c0]; v0.y += bias[c0+1];
                    v1.x += bias[c0]; v1.y += bias[c0+1];
                }
                if (RES) {
                    float2 r0v = *(const float2*)&res[(size_t)r0 * N + c0];
                    float2 r1v = *(const float2*)&res[(size_t)(r0+8) * N + c0];
                    v0.x += r0v.x; v0.y += r0v.y;
                    v1.x += r1v.x; v1.y += r1v.y;
                }
                if (ROPE) {
                    int i = (c0 & 63) >> 1;
                    int t0 = r0 & (PT - 1);
                    int t1 = (r0 + 8) & (PT - 1);
                    float2 cs0 = *(const float2*)&rtab[2*(t0*32 + i)];
                    float2 cs1 = *(const float2*)&rtab[2*(t1*32 + i)];
                    float x0 = v0.x, x1 = v0.y;
                    v0.x = x0*cs0.x - x1*cs0.y;
                    v0.y = x0*cs0.y + x1*cs0.x;
                    x0 = v1.x; x1 = v1.y;
                    v1.x = x0*cs1.x - x1*cs1.y;
                    v1.y = x0*cs1.y + x1*cs1.x;
                }
                *(float2*)&C[(size_t)r0 * N + c0]     = v0;
                *(float2*)&C[(size_t)(r0+8) * N + c0] = v1;
            }
        }
        __syncthreads();
    }
}

// ---------------- RMSNorm ----------------
__global__ void rmsnorm_kernel(const float* __restrict__ x,
                               const float* __restrict__ s1, float* __restrict__ o1,
                               const float* __restrict__ s2, float* __restrict__ o2)
{
    int row = blockIdx.x, tid = threadIdx.x;
    const float* xr = x + (size_t)row * PD;
    float v0 = xr[tid], v1 = xr[tid + 256];
    __shared__ float sred[256];
    sred[tid] = v0*v0 + v1*v1;
    __syncthreads();
    for (int s = 128; s >= 1; s >>= 1) {
        if (tid < s) sred[tid] += sred[tid + s];
        __syncthreads();
    }
    float inv = rsqrtf(sred[0] * (1.0f/512.0f) + 1e-6f);
    size_t base = (size_t)row * PD;
    o1[base + tid]       = v0 * inv * s1[tid];
    o1[base + tid + 256] = v1 * inv * s1[tid + 256];
    if (o2) {
        o2[base + tid]       = v0 * inv * s2[tid];
        o2[base + tid + 256] = v1 * inv * s2[tid + 256];
    }
}

// ---------------- RoPE table ----------------
__global__ void rope_table_kernel(float* __restrict__ tab)
{
    int idx = blockIdx.x * 256 + threadIdx.x;
    int t = idx >> 5, i = idx & 31;
    double freq = exp(-((double)(2*i) / 64.0) * 9.210340371976184);
    double ang = (double)t * freq;
    tab[2*idx    ] = (float)cos(ang);
    tab[2*idx + 1] = (float)sin(ang);
}

// ---------------- causal attention: R12 proven (32-key tiles, float4 reads) ----
__global__ void __launch_bounds__(128) attn_kernel(
    const float* __restrict__ q, const float* __restrict__ k,
    const float* __restrict__ v, float* __restrict__ o)
{
    const int BS = 32;
    __shared__ float Ks[BS][64];
    __shared__ float Vs[BS][64];
    int t = blockIdx.x * 128 + threadIdx.x;
    int h = blockIdx.y, b = blockIdx.z;
    const float* qrow = q + ((size_t)(b*PT + t) * PD + h*PDH);
    float qreg[64];
#pragma unroll
    for (int i = 0; i < 64; i++) qreg[i] = qrow[i];
    float m = -1e30f, l = 0.0f;
    float acc[64];
#pragma unroll
    for (int i = 0; i < 64; i++) acc[i] = 0.0f;

    int send = blockIdx.x * 128 + 128;
    for (int s0 = 0; s0 < send; s0 += BS) {
        __syncthreads();
        for (int i = threadIdx.x; i < BS*16; i += 128) {
            int rr = i >> 4; int cc = (i & 15) << 2;
            size_t goff = (size_t)(b*PT + s0 + rr) * PD + h*PDH + cc;
            *(float4*)&Ks[rr][cc] = *(const float4*)&k[goff];
            *(float4*)&Vs[rr][cc] = *(const float4*)&v[goff];
        }
        __syncthreads();
        int nval = t - s0 + 1;
        if (nval > BS) nval = BS;
        if (nval > 0) {
            float sc[BS];
            float tm = -1e30f;
#pragma unroll
            for (int j = 0; j < BS; j++) {
                float s = 0.0f;
#pragma unroll
                for (int d4 = 0; d4 < 16; d4++) {
                    float4 kv = *(const float4*)&Ks[j][d4*4];
                    s = fmaf(qreg[4*d4+0], kv.x, s);
                    s = fmaf(qreg[4*d4+1], kv.y, s);
                    s = fmaf(qreg[4*d4+2], kv.z, s);
                    s = fmaf(qreg[4*d4+3], kv.w, s);
                }
                s *= 0.125f;
                sc[j] = (j < nval) ? s : -1e30f;
                tm = fmaxf(tm, sc[j]);
            }
            float nm = fmaxf(m, tm);
            float csc = expf(m - nm);
            l *= csc;
#pragma unroll
            for (int d = 0; d < 64; d++) acc[d] *= csc;
#pragma unroll
            for (int j = 0; j < BS; j++) {
                float p = expf(sc[j] - nm);
                l += p;
#pragma unroll
                for (int d4 = 0; d4 < 16; d4++) {
                    float4 vv = *(const float4*)&Vs[j][d4*4];
                    acc[4*d4+0] = fmaf(p, vv.x, acc[4*d4+0]);
                    acc[4*d4+1] = fmaf(p, vv.y, acc[4*d4+1]);
                    acc[4*d4+2] = fmaf(p, vv.z, acc[4*d4+2]);
                    acc[4*d4+3] = fmaf(p, vv.w, acc[4*d4+3]);
                }
            }
            m = nm;
        }
    }
    float inv = 1.0f / l;
    float* orow = o + ((size_t)(b*PT + t) * PD + h*PDH);
#pragma unroll
    for (int i = 0; i < 64; i++) orow[i] = acc[i] * inv;
}

// ---------------- mean over T: two-stage f64 ----------------
__global__ void qwin_part_kernel(const float* __restrict__ h2, double* __restrict__ part)
{
    int b = blockIdx.y, chunk = blockIdx.x, d = threadIdx.x;
    double s = 0.0;
    int t0 = chunk * 64;
    for (int t = t0; t < t0 + 64; t++)
        s += (double)h2[((size_t)(b*PT + t)) * PD + d];
    part[((size_t)b*8 + chunk) * PD + d] = s;
}
__global__ void qwin_reduce_kernel(const double* __restrict__ part, double* __restrict__ qwin)
{
    int b = blockIdx.x, d = threadIdx.x;
    double s = 0.0;
    for (int c = 0; c < 8; c++) s += part[((size_t)b*8 + c) * PD + d];
    qwin[b*PD + d] = s * (1.0 / (double)PT);
}

// ---------------- episodic memory: Kahan-f32 heavy math, f64 scalars ----------------
__global__ void __launch_bounds__(512) episodic_kernel(
    const float* __restrict__ epi_keys, const float* __restrict__ epi_vals,
    const float* __restrict__ epi_age,  const float* __restrict__ epi_str,
    const float* __restrict__ rms_read,
    const float* __restrict__ Wwk, const float* __restrict__ bwk,
    const float* __restrict__ Wwv, const float* __restrict__ bwv,
    const float* __restrict__ Wws, const float* __restrict__ bws,
    const float* __restrict__ Wg1, const float* __restrict__ bg1,
    const float* __restrict__ Wg2, const float* __restrict__ bg2,
    const double* __restrict__ qwin,
    float* __restrict__ read_out,
    float* __restrict__ keys_new, float* __restrict__ vals_new,
    float* __restrict__ age_new,  float* __restrict__ sn_out,
    float* __restrict__ gate_out)
{
    int b = blockIdx.x;
    int tid = threadIdx.x;
    int warp = tid >> 5, lane = tid & 31;
    __shared__ float  qwf[512], wkf[512], wvf[512];
    __shared__ double sred[512];
    __shared__ double lg[64], wr[64];
    __shared__ float  swf[64];
    __shared__ double s_qninv, s_ws, s_wkinv;
    __shared__ float  s_best;
    __shared__ int    s_kstar;

    double qwd = qwin[b*PD + tid];
    qwf[tid] = (float)qwd;
    __syncthreads();

    sred[tid] = qwd*qwd;
    __syncthreads();
    for (int s = 256; s >= 1; s >>= 1) { if (tid < s) sred[tid] += sred[tid+s]; __syncthreads(); }
    if (tid == 0) s_qninv = 1.0 / (sqrt(sred[0]) + 1e-6);
    __syncthreads();

    {
        float a1 = 0.f, c1 = 0.f, a2 = 0.f, c2 = 0.f;
        for (int i = 0; i < 512; i++) {
            float qv = qwf[i];
            kahan_add(a1, c1, __fmul_rn(qv, Wwk[i*512 + tid]));
            kahan_add(a2, c2, __fmul_rn(qv, Wwv[i*512 + tid]));
        }
        wkf[tid] = __fadd_rn(a1, bwk[tid]);
        wvf[tid] = __fadd_rn(a2, bwv[tid]);
    }

    sred[tid] = qwd * (double)Wws[tid];
    __syncthreads();
    for (int s = 256; s >= 1; s >>= 1) { if (tid < s) sred[tid] += sred[tid+s]; __syncthreads(); }
    if (tid == 0) s_ws = 1.0 / (1.0 + exp(-(sred[0] + (double)bws[0])));
    __syncthreads();

    sred[tid] = (double)wkf[tid] * (double)wkf[tid];
    __syncthreads();
    for (int s = 256; s >= 1; s >>= 1) { if (tid < s) sred[tid] += sred[tid+s]; __syncthreads(); }
    if (tid == 0) s_wkinv = 1.0 / (sqrt(sred[0]) + 1e-6);
    __syncthreads();

    for (int kk = warp; kk < PK; kk += 16) {
        const float* kp = epi_keys + (size_t)(b*PK + kk) * PD;
        float ss = 0.f, ssc = 0.f, dq = 0.f, dqc = 0.f, dw = 0.f, dwc = 0.f;
        for (int d = lane; d < 512; d += 32) {
            float kv = kp[d];
            kahan_add(ss, ssc, __fmul_rn(kv, kv));
            kahan_add(dq, dqc, __fmul_rn(kv, qwf[d]));
            kahan_add(dw, dwc, __fmul_rn(kv, wkf[d]));
        }
#pragma unroll
        for (int o = 16; o > 0; o >>= 1) {
            ss += __shfl_xor_sync(0xffffffffu, ss, o);
            dq += __shfl_xor_sync(0xffffffffu, dq, o);
            dw += __shfl_xor_sync(0xffffffffu, dw, o);
        }
        if (lane == 0) {
            double kninv = 1.0 / (sqrt((double)ss) + 1e-6);
            double simr  = (double)dq * kninv * s_qninv;
            double st    = (double)epi_str[b*PK + kk];
            double stc   = fmin(fmax(st, 0.001), 1e9);
            lg[kk] = simr + 0.5*log(stc) - 0.02*(double)epi_age[b*PK + kk]
                   + ((st > 0.001) ? 0.0 : -1000.0);
            swf[kk] = (float)((double)dw * kninv * s_wkinv);
        }
    }
    __syncthreads();

    if (tid == 0) {
        double mx = -1e300;
        for (int kk = 0; kk < PK; kk++) mx = fmax(mx, lg[kk]);
        double sm = 0.0;
        for (int kk = 0; kk < PK; kk++) { double e = exp(lg[kk]-mx); wr[kk] = e; sm += e; }
        double inv = 1.0 / sm;
        for (int kk = 0; kk < PK; kk++) wr[kk] *= inv;
        float bs = -1e30f; int kst = 0;
        for (int kk = 0; kk < PK; kk++) if (swf[kk] > bs) { bs = swf[kk]; kst = kk; }
        s_best = bs; s_kstar = kst;
    }
    __syncthreads();

    float r = 0.f, rc = 0.f;
    for (int kk = 0; kk < PK; kk++)
        kahan_add(r, rc, __fmul_rn((float)wr[kk], epi_vals[(size_t)(b*PK + kk)*PD + tid]));
    sred[tid] = (double)r * (double)r;
    __syncthreads();
    for (int s = 256; s >= 1; s >>= 1) { if (tid < s) sred[tid] += sred[tid+s]; __syncthreads(); }
    double rinv = 1.0 / sqrt(sred[0] * (1.0/512.0) + 1e-6);
    read_out[b*PD + tid] = (float)((double)r * rinv * (double)rms_read[tid]);
    __syncthreads();

    float ws = (float)s_ws; int kstar = s_kstar;

    for (int kk = warp; kk < PK; kk += 16) {
        float re = (kk == kstar) ? ws * 0.5f : 0.0f;
        const float* kp = epi_keys + (size_t)(b*PK + kk) * PD;
        const float* vp = epi_vals + (size_t)(b*PK + kk) * PD;
        float ss = 0.f;
        for (int d = lane; d < 512; d += 32) {
            float tk = (1.0f - re)*kp[d] + re*wkf[d];
            ss = fmaf(tk, tk, ss);
            vals_new[(size_t)(b*PK + kk)*PD + d] = (1.0f - re)*vp[d] + re*wvf[d];
        }
#pragma unroll
        for (int o = 16; o > 0; o >>= 1) ss += __shfl_xor_sync(0xffffffffu, ss, o);
        float ninv = (float)(1.0 / (sqrt((double)ss) + 1e-6));
        for (int d = lane; d < 512; d += 32) {
            float tk = (1.0f - re)*kp[d] + re*wkf[d];
            keys_new[(size_t)(b*PK + kk)*PD + d] = tk * ninv;
        }
    }

    if (tid < PK) {
        int kk = tid;
        float ww = (kk == kstar) ? 1.0f : 0.0f;
        age_new[b*PK + kk] = (epi_age[b*PK + kk] + 1.0f) * (1.0f - ww);
        float s0 = epi_str[b*PK + kk] * 0.995f;
        float snv = s0 + ww * ws * (1.0f - s0);
        sn_out[b*PK + kk] = fminf(fmaxf(snv, 0.001f), 1.0f);
    }

    {
        float nov = 1.0f - s_best;
        float hs = 0.f, hc = 0.f;
        for (int i = 0; i < 512; i++)
            kahan_add(hs, hc, __fmul_rn(qwf[i], Wg1[i*512 + tid]));
        kahan_add(hs, hc, __fmul_rn(ws,  Wg1[512*512 + tid]));
        kahan_add(hs, hc, __fmul_rn(nov, Wg1[513*512 + tid]));
        double hsum = (double)__fadd_rn(hs, bg1[tid]);
        double sil = hsum / (1.0 + exp(-hsum));
        sred[tid] = sil * (double)Wg2[tid];
    }
    __syncthreads();
    for (int s = 256; s >= 1; s >>= 1) { if (tid < s) sred[tid] += sred[tid+s]; __syncthreads(); }
    if (tid == 0) gate_out[b] = (float)(1.0 / (1.0 + exp(-(sred[0] + (double)bg2[0]))));
}

// ---------------- out += gate[b] * read[b, :] ----------------
__global__ void bcast_add_kernel(float* __restrict__ out,
                                 const float* __restrict__ read,
                                 const float* __restrict__ gate)
{
    size_t idx = (size_t)blockIdx.x * blockDim.x + threadIdx.x;
    int b = (int)(idx >> 18);
    int d = (int)(idx & 511);
    out[idx] += gate[b] * read[b*PD + d];
}

// ---------------- launch ----------------
extern "C" void kernel_launch(void* const* d_in, const int* in_sizes, int n_in,
                              void* d_out, int out_size)
{
    const float* x        = (const float*)d_in[0];
    const float* epi_keys = (const float*)d_in[1];
    const float* epi_vals = (const float*)d_in[2];
    const float* epi_age  = (const float*)d_in[3];
    const float* epi_str  = (const float*)d_in[4];
    const float* rms1     = (const float*)d_in[6];
    const float* rms_kv   = (const float*)d_in[7];
    const float* rms2     = (const float*)d_in[8];
    const float* rms_read = (const float*)d_in[9];
    const float* Wq = (const float*)d_in[10]; const float* bq = (const float*)d_in[11];
    const float* Wk = (const float*)d_in[12]; const float* bk = (const float*)d_in[13];
    const float* Wv = (const float*)d_in[14]; const float* bv = (const float*)d_in[15];
    const float* Wo = (const float*)d_in[16]; const float* bo = (const float*)d_in[17];
    const float* W1 = (const float*)d_in[18]; const float* W2 = (const float*)d_in[19];
    const float* Wwk = (const float*)d_in[20]; const float* bwk = (const float*)d_in[21];
    const float* Wwv = (const float*)d_in[22]; const float* bwv = (const float*)d_in[23];
    const float* Wws = (const float*)d_in[24]; const float* bws = (const float*)d_in[25];
    const float* Wg1 = (const float*)d_in[26]; const float* bg1 = (const float*)d_in[27];
    const float* Wg2 = (const float*)d_in[28]; const float* bg2 = (const float*)d_in[29];

    float *nx, *nkv, *q, *k, *v, *o, *h1, *nh1, *gv, *readb, *ropetab;
    double *qwin, *qpart;
    cudaGetSymbolAddress((void**)&nx,   g_nx);
    cudaGetSymbolAddress((void**)&nkv,  g_nkv);
    cudaGetSymbolAddress((void**)&q,    g_q);
    cudaGetSymbolAddress((void**)&k,    g_k);
    cudaGetSymbolAddress((void**)&v,    g_v);
    cudaGetSymbolAddress((void**)&o,    g_o);
    cudaGetSymbolAddress((void**)&h1,   g_h1);
    cudaGetSymbolAddress((void**)&nh1,  g_nh1);
    cudaGetSymbolAddress((void**)&gv,   g_gv);
    cudaGetSymbolAddress((void**)&qwin, g_qwin);
    cudaGetSymbolAddress((void**)&qpart,g_qpart);
    cudaGetSymbolAddress((void**)&readb,g_read);
    cudaGetSymbolAddress((void**)&ropetab, g_rope);

    float* out      = (float*)d_out;
    float* keys_new = out + (size_t)ROWS*PD;
    float* vals_new = keys_new + (size_t)PB*PK*PD;
    float* age_new  = vals_new + (size_t)PB*PK*PD;
    float* sn       = age_new + PB*PK;
    float* gate     = sn + PB*PK;

    cudaFuncSetAttribute(mma_gemm_kernel<true,false,true,false>,
                         cudaFuncAttributeMaxDynamicSharedMemorySize, GSMEM_BYTES);
    cudaFuncSetAttribute(mma_gemm_kernel<true,false,false,false>,
                         cudaFuncAttributeMaxDynamicSharedMemorySize, GSMEM_BYTES);
    cudaFuncSetAttribute(mma_gemm_kernel<true,true,false,false>,
                         cudaFuncAttributeMaxDynamicSharedMemorySize, GSMEM_BYTES);
    cudaFuncSetAttribute(mma_gemm_kernel<false,false,false,false>,
                         cudaFuncAttributeMaxDynamicSharedMemorySize, GSMEM_BYTES);
    cudaFuncSetAttribute(mma_gemm_kernel<false,true,false,true>,
                         cudaFuncAttributeMaxDynamicSharedMemorySize, GSMEM_BYTES);

    dim3 blk(256);
    dim3 pgrid(GEMM_GRID);

    rope_table_kernel<<<64, 256>>>(ropetab);
    rmsnorm_kernel<<<ROWS, 256>>>(x, rms1, nx, rms_kv, nkv);
    mma_gemm_kernel<true,false,true,false><<<pgrid, blk, GSMEM_BYTES>>>(
        nx,  nullptr, Wq, bq, nullptr, ropetab, q, ROWS, 512, 512, 512);
    mma_gemm_kernel<true,false,true,false><<<pgrid, blk, GSMEM_BYTES>>>(
        nkv, nullptr, Wk, bk, nullptr, ropetab, k, ROWS, 512, 512, 512);
    mma_gemm_kernel<true,false,false,false><<<pgrid, blk, GSMEM_BYTES>>>(
        nkv, nullptr, Wv, bv, nullptr, nullptr, v, ROWS, 512, 512, 512);
    attn_kernel<<<dim3(PT/128, PH, PB), 128>>>(q, k, v, o);
    mma_gemm_kernel<true,true,false,false><<<pgrid, blk, GSMEM_BYTES>>>(
        o, nullptr, Wo, bo, x, nullptr, h1, ROWS, 512, 512, 512);
    rmsnorm_kernel<<<ROWS, 256>>>(h1, rms2, nh1, nullptr, nullptr);
    mma_gemm_kernel<false,false,false,false><<<pgrid, blk, GSMEM_BYTES>>>(
        nh1, nullptr, W1, nullptr, nullptr, nullptr, gv, ROWS, 4096, 512, 512);
    mma_gemm_kernel<false,true,false,true><<<pgrid, blk, GSMEM_BYTES>>>(
        gv, gv + 2048, W2, nullptr, h1, nullptr, out, ROWS, 512, 2048, 4096);
    qwin_part_kernel<<<dim3(8, PB), 512>>>(out, qpart);
    qwin_reduce_kernel<<<PB, 512>>>(qpart, qwin);
    episodic_kernel<<<PB, 512>>>(epi_keys, epi_vals, epi_age, epi_str, rms_read,
                                 Wwk, bwk, Wwv, bwv, Wws, bws, Wg1, bg1, Wg2, bg2,
                                 qwin, readb, keys_new, vals_new, age_new, sn, gate);
    bcast_add_kernel<<<(ROWS*PD)/256, 256>>>(out, readb, gate);
}